// round 14
// baseline (speedup 1.0000x reference)
#include <cuda_runtime.h>
#include <cuda_bf16.h>
#include <cstdint>

// Model dims
#define Lc   4
#define Dc   2048
#define Hc   16
#define HDc  128
#define Ic   5632
#define Vc   32000
#define Bc   2
#define Sc   1024
#define Tc   (Bc*Sc)        // 2048 tokens
#define QKVc (3*Hc*HDc)     // 6144
#define GUc  (2*Ic)         // 11264

// ---------------- scratch (static device globals; no allocations) ----------
__device__ float g_h  [Tc*Dc];     // residual (fp32)
__device__ float g_qkv[Tc*QKVc];   // qkv fp32 (attention input)

// split activations (bf16 hi/lo)
__device__ __nv_bfloat16 g_xh[Tc*Dc],  g_xl[Tc*Dc];
__device__ __nv_bfloat16 g_oh[Tc*Dc],  g_ol[Tc*Dc];
__device__ __nv_bfloat16 g_ah[Tc*Ic],  g_al[Tc*Ic];

// split weights (bf16 hi/lo); Wgu is stored gate/up row-interleaved
__device__ __nv_bfloat16 g_wqkvh[Lc*QKVc*Dc], g_wqkvl[Lc*QKVc*Dc];
__device__ __nv_bfloat16 g_woh  [Lc*Dc*Dc],   g_wol  [Lc*Dc*Dc];
__device__ __nv_bfloat16 g_wguh [Lc*GUc*Dc],  g_wgul [Lc*GUc*Dc];
__device__ __nv_bfloat16 g_wdh  [Lc*Dc*Ic],   g_wdl  [Lc*Dc*Ic];
__device__ __nv_bfloat16 g_lmhh [Vc*Dc],      g_lmhl [Vc*Dc];

// ---------------- small helpers --------------------------------------------
__device__ __forceinline__ uint32_t smem_u32(const void* p) {
    uint32_t a;
    asm("{ .reg .u64 t; cvta.to.shared.u64 t, %1; cvt.u32.u64 %0, t; }"
        : "=r"(a) : "l"(p));
    return a;
}
__device__ __forceinline__ void split_store4(__nv_bfloat16* hp, __nv_bfloat16* lp,
                                             long long off, float4 v) {
    __nv_bfloat16 h0 = __float2bfloat16(v.x), h1 = __float2bfloat16(v.y);
    __nv_bfloat16 h2 = __float2bfloat16(v.z), h3 = __float2bfloat16(v.w);
    __nv_bfloat16 l0 = __float2bfloat16(v.x - __bfloat162float(h0));
    __nv_bfloat16 l1 = __float2bfloat16(v.y - __bfloat162float(h1));
    __nv_bfloat16 l2 = __float2bfloat16(v.z - __bfloat162float(h2));
    __nv_bfloat16 l3 = __float2bfloat16(v.w - __bfloat162float(h3));
    *(ushort4*)(hp + off) = make_ushort4(__bfloat16_as_ushort(h0), __bfloat16_as_ushort(h1),
                                         __bfloat16_as_ushort(h2), __bfloat16_as_ushort(h3));
    *(ushort4*)(lp + off) = make_ushort4(__bfloat16_as_ushort(l0), __bfloat16_as_ushort(l1),
                                         __bfloat16_as_ushort(l2), __bfloat16_as_ushort(l3));
}
__device__ __forceinline__ void split_pack2(float a, float b,
                                            uint32_t& h, uint32_t& l) {
    __nv_bfloat16 ha = __float2bfloat16(a), hb = __float2bfloat16(b);
    __nv_bfloat16 la = __float2bfloat16(a - __bfloat162float(ha));
    __nv_bfloat16 lb = __float2bfloat16(b - __bfloat162float(hb));
    h = (uint32_t)__bfloat16_as_ushort(ha) | ((uint32_t)__bfloat16_as_ushort(hb) << 16);
    l = (uint32_t)__bfloat16_as_ushort(la) | ((uint32_t)__bfloat16_as_ushort(lb) << 16);
}

// ---------------- weight split ---------------------------------------------
__global__ void split_kernel(const float* __restrict__ s,
                             __nv_bfloat16* __restrict__ hp,
                             __nv_bfloat16* __restrict__ lp, long long n) {
    long long i = ((long long)blockIdx.x * blockDim.x + threadIdx.x) * 4;
    if (i >= n) return;
    split_store4(hp, lp, i, *(const float4*)(s + i));
}

// Wgu split with gate/up row interleave: dst row 2j = gate j, 2j+1 = up j.
__global__ void split_wgu_kernel(const float* __restrict__ s,
                                 __nv_bfloat16* __restrict__ hp,
                                 __nv_bfloat16* __restrict__ lp) {
    const long long total = (long long)Lc * GUc * Dc;
    long long i = ((long long)blockIdx.x * blockDim.x + threadIdx.x) * 4;
    if (i >= total) return;
    const long long layer = i / ((long long)GUc * Dc);
    const long long rem   = i - layer * (long long)GUc * Dc;
    const int nr = (int)(rem / Dc);          // interleaved dst row
    const int k  = (int)(rem - (long long)nr * Dc);
    const int sr = (nr & 1) ? (Ic + (nr >> 1)) : (nr >> 1);
    const long long src = layer * (long long)GUc * Dc + (long long)sr * Dc + k;
    split_store4(hp, lp, i, *(const float4*)(s + src));
}

// ---------------- embedding gather -----------------------------------------
__global__ void embed_kernel(const int* __restrict__ ids,
                             const float* __restrict__ emb,
                             float* __restrict__ h) {
    const int t = blockIdx.x;
    const int id = ids[t];
    const float4* src = (const float4*)(emb + (long long)id * Dc);
    float4* dst = (float4*)(h + (long long)t * Dc);
    for (int i = threadIdx.x; i < Dc / 4; i += blockDim.x) dst[i] = src[i];
}

// ---------------- rmsnorm -> split bf16 -------------------------------------
__global__ void __launch_bounds__(256) rmsnorm_kernel(
    __nv_bfloat16* __restrict__ oh, __nv_bfloat16* __restrict__ ol,
    const float* __restrict__ in, const float* __restrict__ w) {
    const int t = blockIdx.x;
    const int tid = threadIdx.x;
    const float4* row = (const float4*)(in + (long long)t * Dc);
    float4 v0 = row[tid];
    float4 v1 = row[tid + 256];
    float ss = v0.x*v0.x + v0.y*v0.y + v0.z*v0.z + v0.w*v0.w
             + v1.x*v1.x + v1.y*v1.y + v1.z*v1.z + v1.w*v1.w;
    #pragma unroll
    for (int m = 16; m >= 1; m >>= 1) ss += __shfl_xor_sync(0xffffffffu, ss, m);
    __shared__ float red[8];
    __shared__ float s_inv;
    if ((tid & 31) == 0) red[tid >> 5] = ss;
    __syncthreads();
    if (tid == 0) {
        float tot = 0.f;
        #pragma unroll
        for (int i = 0; i < 8; ++i) tot += red[i];
        s_inv = rsqrtf(tot * (1.0f / (float)Dc) + 1e-6f);
    }
    __syncthreads();
    const float inv = s_inv;
    const float4* wv = (const float4*)w;
    float4 w0 = wv[tid], w1 = wv[tid + 256];
    float4 o0 = make_float4(v0.x*inv*w0.x, v0.y*inv*w0.y, v0.z*inv*w0.z, v0.w*inv*w0.w);
    float4 o1 = make_float4(v1.x*inv*w1.x, v1.y*inv*w1.y, v1.z*inv*w1.z, v1.w*inv*w1.w);
    const long long base = (long long)t * Dc;
    split_store4(oh, ol, base + tid * 4, o0);
    split_store4(oh, ol, base + (tid + 256) * 4, o1);
}

// ---------------- rope ------------------------------------------------------
__global__ void rope_kernel(float* __restrict__ qkv, const int* __restrict__ pos) {
    const int idx = blockIdx.x * blockDim.x + threadIdx.x;
    if (idx >= Tc * Hc * (HDc / 2)) return;
    const int i  = idx & 63;
    const int hh = (idx >> 6) & (Hc - 1);
    const int t  = idx >> 10;
    const float freq = expf(-(float)i * (9.210340371976184f / 64.0f));
    const float ang  = (float)pos[t & (Sc - 1)] * freq;
    float s, c;
    sincosf(ang, &s, &c);
    const long long base = (long long)t * QKVc + hh * HDc + i;
    float q1 = qkv[base], q2 = qkv[base + 64];
    qkv[base]      = q1 * c - q2 * s;
    qkv[base + 64] = q2 * c + q1 * s;
    const long long kb = base + Dc;
    float k1 = qkv[kb], k2 = qkv[kb + 64];
    qkv[kb]      = k1 * c - k2 * s;
    qkv[kb + 64] = k2 * c + k1 * s;
}

// ---------------- bf16x3 NT GEMM: 4 warps, warp tile 64x64 ------------------
// C[M,N] (+=) (Ah+Al)[M,K]*(Bh+Bl)[N,K]^T; D += Ah*Bh + Ah*Bl + Al*Bh.
// mode 0: store C; 1: C += ; 2: silu-fused (gate/up interleaved cols) -> Oh/Ol.
#define PITCH       80
#define TILE_BYTES  (128*PITCH)      // 10240
#define STAGE_BYTES (4*TILE_BYTES)   // 40960: Ah, Al, Bh, Bl
#define GEMM_SMEM   (2*STAGE_BYTES)  // 81920 -> 2 CTAs/SM

__device__ __forceinline__ void cp16(uint32_t dst, const void* src) {
    asm volatile("cp.async.cg.shared.global [%0], [%1], 16;" :: "r"(dst), "l"(src));
}
__device__ __forceinline__ void ldsm4(uint32_t* r, uint32_t addr) {
    asm volatile("ldmatrix.sync.aligned.m8n8.x4.shared.b16 {%0,%1,%2,%3}, [%4];"
                 : "=r"(r[0]), "=r"(r[1]), "=r"(r[2]), "=r"(r[3]) : "r"(addr));
}
__device__ __forceinline__ void ldsm2(uint32_t* r, uint32_t addr) {
    asm volatile("ldmatrix.sync.aligned.m8n8.x2.shared.b16 {%0,%1}, [%2];"
                 : "=r"(r[0]), "=r"(r[1]) : "r"(addr));
}
__device__ __forceinline__ void mma_bf16(float* c, const uint32_t* a, const uint32_t* b) {
    asm volatile(
        "mma.sync.aligned.m16n8k16.row.col.f32.bf16.bf16.f32 "
        "{%0,%1,%2,%3}, {%4,%5,%6,%7}, {%8,%9}, {%0,%1,%2,%3};"
        : "+f"(c[0]), "+f"(c[1]), "+f"(c[2]), "+f"(c[3])
        : "r"(a[0]), "r"(a[1]), "r"(a[2]), "r"(a[3]), "r"(b[0]), "r"(b[1]));
}
__device__ __forceinline__ float silu_mul(float g, float u) {
    return (g / (1.f + expf(-g))) * u;
}

__device__ __forceinline__ void load_stage(
    uint32_t sb, int s,
    const __nv_bfloat16* __restrict__ Ah, const __nv_bfloat16* __restrict__ Al,
    const __nv_bfloat16* __restrict__ Bh, const __nv_bfloat16* __restrict__ Bl,
    long long bm, long long bn, long long K, long long k0, int tid) {
    const __nv_bfloat16* gs[4] = {Ah, Al, Bh, Bl};
    #pragma unroll
    for (int t = 0; t < 4; ++t) {
        const long long row0 = (t < 2) ? bm : bn;
        const __nv_bfloat16* g = gs[t];
        #pragma unroll
        for (int u = 0; u < 4; ++u) {
            const int ch = tid + (u << 7);      // 0..511
            const int r = ch >> 2, c = ch & 3;  // row, 16B chunk
            const uint32_t dst = sb + s * STAGE_BYTES + t * TILE_BYTES
                               + r * PITCH + c * 16;
            cp16(dst, g + (row0 + r) * K + k0 + c * 8);
        }
    }
}

__global__ void __launch_bounds__(128) gemm_bf16x3(
    const __nv_bfloat16* __restrict__ Ah, const __nv_bfloat16* __restrict__ Al,
    const __nv_bfloat16* __restrict__ Bh, const __nv_bfloat16* __restrict__ Bl,
    float* __restrict__ C,
    __nv_bfloat16* __restrict__ Oh, __nv_bfloat16* __restrict__ Ol,
    int M, int N, int K, int mode) {
    extern __shared__ char smraw[];
    const uint32_t sb = smem_u32(smraw);
    const int tid  = threadIdx.x;
    const int wid  = tid >> 5;
    const int lane = tid & 31;
    const int grp  = lane >> 2;
    const int qid  = lane & 3;
    const int m_base = (wid >> 1) * 64;    // 0 or 64
    const int n_base = (wid & 1) * 64;     // 0 or 64
    const long long bm = (long long)blockIdx.x * 128;
    const long long bn = (long long)blockIdx.y * 128;

    float acc[4][8][4];
    #pragma unroll
    for (int i = 0; i < 4; ++i)
        #pragma unroll
        for (int j = 0; j < 8; ++j)
            #pragma unroll
            for (int r = 0; r < 4; ++r) acc[i][j][r] = 0.f;

    const int nIter = K >> 5;
    load_stage(sb, 0, Ah, Al, Bh, Bl, bm, bn, K, 0, tid);
    asm volatile("cp.async.commit_group;" ::: "memory");

    const int arow = lane & 15, achunk = lane >> 4;
    const int brow = lane & 7,  bchunk = (lane >> 3) & 1;

    for (int it = 0; it < nIter; ++it) {
        const int s = it & 1;
        if (it + 1 < nIter) {
            load_stage(sb, s ^ 1, Ah, Al, Bh, Bl, bm, bn, K,
                       (long long)(it + 1) << 5, tid);
            asm volatile("cp.async.commit_group;" ::: "memory");
            asm volatile("cp.async.wait_group 1;" ::: "memory");
        } else {
            asm volatile("cp.async.wait_group 0;" ::: "memory");
        }
        __syncthreads();

        const uint32_t stb = sb + s * STAGE_BYTES;
        #pragma unroll
        for (int ks = 0; ks < 2; ++ks) {
            uint32_t ah[4][4], al[4][4], bh[8][2], bl[8][2];
            #pragma unroll
            for (int mt = 0; mt < 4; ++mt) {
                const uint32_t ad = stb + (m_base + mt * 16 + arow) * PITCH
                                  + (ks * 2 + achunk) * 16;
                ldsm4(ah[mt], ad);
                ldsm4(al[mt], ad + TILE_BYTES);
            }
            #pragma unroll
            for (int nt = 0; nt < 8; ++nt) {
                const uint32_t bd = stb + 2 * TILE_BYTES
                                  + (n_base + nt * 8 + brow) * PITCH
                                  + (ks * 2 + bchunk) * 16;
                ldsm2(bh[nt], bd);
                ldsm2(bl[nt], bd + TILE_BYTES);
            }
            #pragma unroll
            for (int mt = 0; mt < 4; ++mt)
                #pragma unroll
                for (int nt = 0; nt < 8; ++nt) {
                    mma_bf16(acc[mt][nt], ah[mt], bh[nt]);
                    mma_bf16(acc[mt][nt], ah[mt], bl[nt]);
                    mma_bf16(acc[mt][nt], al[mt], bh[nt]);
                }
        }
        __syncthreads();
    }

    if (mode == 2) {
        // silu-fused: even col = gate, odd col = up; output width N/2
        const int NO = N >> 1;
        #pragma unroll
        for (int mt = 0; mt < 4; ++mt) {
            #pragma unroll
            for (int nt = 0; nt < 8; ++nt) {
                const long long row = bm + m_base + mt * 16 + grp;
                const long long col = (bn + n_base + nt * 8 + 2 * qid) >> 1;
                float* c = acc[mt][nt];
                const float a0 = silu_mul(c[0], c[1]);
                const float a1 = silu_mul(c[2], c[3]);
                __nv_bfloat16 h0 = __float2bfloat16(a0);
                __nv_bfloat16 l0 = __float2bfloat16(a0 - __bfloat162float(h0));
                __nv_bfloat16 h1 = __float2bfloat16(a1);
                __nv_bfloat16 l1 = __float2bfloat16(a1 - __bfloat162float(h1));
                Oh[row * NO + col] = h0;  Ol[row * NO + col] = l0;
                Oh[(row + 8) * NO + col] = h1;  Ol[(row + 8) * NO + col] = l1;
            }
        }
        return;
    }

    #pragma unroll
    for (int mt = 0; mt < 4; ++mt) {
        #pragma unroll
        for (int nt = 0; nt < 8; ++nt) {
            const long long row = bm + m_base + mt * 16 + grp;
            const long long col = bn + n_base + nt * 8 + 2 * qid;
            float* c = acc[mt][nt];
            if (mode == 1) {
                float2 r0 = *(const float2*)&C[row * N + col];
                float2 r1 = *(const float2*)&C[(row + 8) * N + col];
                c[0] += r0.x; c[1] += r0.y; c[2] += r1.x; c[3] += r1.y;
            }
            *(float2*)&C[row * N + col]       = make_float2(c[0], c[1]);
            *(float2*)&C[(row + 8) * N + col] = make_float2(c[2], c[3]);
        }
    }
}

// ---------------- tensor-core flash attention (bf16x3) ----------------------
#define AQP 272   // Q row pitch: 128 bf16 = 256B + 16 pad
#define AKP 272   // K row pitch
#define AVP 144   // V^T row pitch: 64 bf16 = 128B + 16 pad
#define OFF_QH 0
#define OFF_QL (128*AQP)
#define OFF_KH (2*128*AQP)
#define OFF_KL (OFF_KH + 64*AKP)
#define OFF_VH (OFF_KL + 64*AKP)
#define OFF_VL (OFF_VH + 128*AVP)
#define ATTN_SMEM (OFF_VL + 128*AVP)   // 141312 bytes

__global__ void __launch_bounds__(256) attn_kernel(
    const float* __restrict__ qkv,
    __nv_bfloat16* __restrict__ oh, __nv_bfloat16* __restrict__ ol) {
    extern __shared__ char sm[];
    const uint32_t sb = smem_u32(sm);
    const int tid = threadIdx.x, wid = tid >> 5, lane = tid & 31;
    const int grp = lane >> 2, qid = lane & 3;
    const int qt = (int)gridDim.x - 1 - (int)blockIdx.x;  // heavy first
    const int hh = blockIdx.y, b = blockIdx.z;
    const int q0 = qt * 128;
    const int tok0 = b * Sc + q0;
    const float scale = 0.08838834764831845f;

    for (int idx = tid; idx < 128 * 128; idx += 256) {
        const int r = idx >> 7, d = idx & 127;
        const float v = qkv[(long long)(tok0 + r) * QKVc + hh * HDc + d] * scale;
        const __nv_bfloat16 h = __float2bfloat16(v);
        const __nv_bfloat16 l = __float2bfloat16(v - __bfloat162float(h));
        *(unsigned short*)(sm + OFF_QH + r * AQP + d * 2) = __bfloat16_as_ushort(h);
        *(unsigned short*)(sm + OFF_QL + r * AQP + d * 2) = __bfloat16_as_ushort(l);
    }

    float of[16][4];
    #pragma unroll
    for (int n = 0; n < 16; ++n)
        #pragma unroll
        for (int r = 0; r < 4; ++r) of[n][r] = 0.f;
    float m0 = -3.0e38f, m1 = -3.0e38f, l0 = 0.f, l1 = 0.f;

    const int arow = lane & 15, achunk = lane >> 4;
    const int brow = lane & 7,  bchunk = (lane >> 3) & 1;
    const int rb = q0 + wid * 16;
    const int n_tiles = (q0 >> 6) + 2;

    for (int kt = 0; kt < n_tiles; ++kt) {
        __syncthreads();
        const int ktok = b * Sc + kt * 64;
        for (int idx = tid; idx < 64 * 128; idx += 256) {
            const int r = idx >> 7, d = idx & 127;
            const long long gk = (long long)(ktok + r) * QKVc + Dc + hh * HDc + d;
            const float kv = qkv[gk];
            __nv_bfloat16 h = __float2bfloat16(kv);
            __nv_bfloat16 l = __float2bfloat16(kv - __bfloat162float(h));
            *(unsigned short*)(sm + OFF_KH + r * AKP + d * 2) = __bfloat16_as_ushort(h);
            *(unsigned short*)(sm + OFF_KL + r * AKP + d * 2) = __bfloat16_as_ushort(l);
            const float vv = qkv[gk + Dc];
            h = __float2bfloat16(vv);
            l = __float2bfloat16(vv - __bfloat162float(h));
            *(unsigned short*)(sm + OFF_VH + d * AVP + r * 2) = __bfloat16_as_ushort(h);
            *(unsigned short*)(sm + OFF_VL + d * AVP + r * 2) = __bfloat16_as_ushort(l);
        }
        __syncthreads();

        float sfr[8][4];
        #pragma unroll
        for (int j = 0; j < 8; ++j)
            #pragma unroll
            for (int r = 0; r < 4; ++r) sfr[j][r] = 0.f;
        #pragma unroll
        for (int ks = 0; ks < 8; ++ks) {
            uint32_t qh[4], ql[4];
            const uint32_t qa = sb + OFF_QH + (wid * 16 + arow) * AQP + (ks * 2 + achunk) * 16;
            ldsm4(qh, qa);
            ldsm4(ql, qa + (OFF_QL - OFF_QH));
            #pragma unroll
            for (int j = 0; j < 8; ++j) {
                uint32_t kh2[2], kl2[2];
                const uint32_t ka = sb + OFF_KH + (8 * j + brow) * AKP + (ks * 2 + bchunk) * 16;
                ldsm2(kh2, ka);
                ldsm2(kl2, ka + (OFF_KL - OFF_KH));
                mma_bf16(sfr[j], qh, kh2);
                mma_bf16(sfr[j], qh, kl2);
                mma_bf16(sfr[j], ql, kh2);
            }
        }

        if (kt * 64 + 63 > rb) {
            #pragma unroll
            for (int j = 0; j < 8; ++j) {
                const int col = kt * 64 + 8 * j + 2 * qid;
                const int r0g = rb + grp, r1g = rb + grp + 8;
                if (col     > r0g) sfr[j][0] = -3.0e38f;
                if (col + 1 > r0g) sfr[j][1] = -3.0e38f;
                if (col     > r1g) sfr[j][2] = -3.0e38f;
                if (col + 1 > r1g) sfr[j][3] = -3.0e38f;
            }
        }

        float ml0 = -3.0e38f, ml1 = -3.0e38f;
        #pragma unroll
        for (int j = 0; j < 8; ++j) {
            ml0 = fmaxf(ml0, fmaxf(sfr[j][0], sfr[j][1]));
            ml1 = fmaxf(ml1, fmaxf(sfr[j][2], sfr[j][3]));
        }
        ml0 = fmaxf(ml0, __shfl_xor_sync(0xffffffffu, ml0, 1));
        ml0 = fmaxf(ml0, __shfl_xor_sync(0xffffffffu, ml0, 2));
        ml1 = fmaxf(ml1, __shfl_xor_sync(0xffffffffu, ml1, 1));
        ml1 = fmaxf(ml1, __shfl_xor_sync(0xffffffffu, ml1, 2));
        const float mn0 = fmaxf(m0, ml0), mn1 = fmaxf(m1, ml1);
        const float sc0 = expf(m0 - mn0), sc1 = expf(m1 - mn1);
        m0 = mn0; m1 = mn1;

        float rs0 = 0.f, rs1 = 0.f;
        uint32_t pah[4][4], pal[4][4];
        #pragma unroll
        for (int t = 0; t < 4; ++t) {
            const float p00 = expf(sfr[2*t][0] - mn0), p01 = expf(sfr[2*t][1] - mn0);
            const float p02 = expf(sfr[2*t][2] - mn1), p03 = expf(sfr[2*t][3] - mn1);
            const float p10 = expf(sfr[2*t+1][0] - mn0), p11 = expf(sfr[2*t+1][1] - mn0);
            const float p12 = expf(sfr[2*t+1][2] - mn1), p13 = expf(sfr[2*t+1][3] - mn1);
            rs0 += p00 + p01 + p10 + p11;
            rs1 += p02 + p03 + p12 + p13;
            split_pack2(p00, p01, pah[t][0], pal[t][0]);
            split_pack2(p02, p03, pah[t][1], pal[t][1]);
            split_pack2(p10, p11, pah[t][2], pal[t][2]);
            split_pack2(p12, p13, pah[t][3], pal[t][3]);
        }
        rs0 += __shfl_xor_sync(0xffffffffu, rs0, 1);
        rs0 += __shfl_xor_sync(0xffffffffu, rs0, 2);
        rs1 += __shfl_xor_sync(0xffffffffu, rs1, 1);
        rs1 += __shfl_xor_sync(0xffffffffu, rs1, 2);
        l0 = l0 * sc0 + rs0;
        l1 = l1 * sc1 + rs1;

        #pragma unroll
        for (int n = 0; n < 16; ++n) {
            of[n][0] *= sc0; of[n][1] *= sc0;
            of[n][2] *= sc1; of[n][3] *= sc1;
        }
        #pragma unroll
        for (int t = 0; t < 4; ++t) {
            #pragma unroll
            for (int n = 0; n < 16; ++n) {
                uint32_t vh2[2], vl2[2];
                const uint32_t va = sb + OFF_VH + (8 * n + brow) * AVP + (t * 2 + bchunk) * 16;
                ldsm2(vh2, va);
                ldsm2(vl2, va + (OFF_VL - OFF_VH));
                mma_bf16(of[n], pah[t], vh2);
                mma_bf16(of[n], pah[t], vl2);
                mma_bf16(of[n], pal[t], vh2);
            }
        }
    }

    const float li0 = 1.f / l0, li1 = 1.f / l1;
    const long long row0 = (long long)(tok0 + wid * 16 + grp);
    #pragma unroll
    for (int n = 0; n < 16; ++n) {
        const long long col = hh * HDc + 8 * n + 2 * qid;
        uint32_t h2, l2;
        split_pack2(of[n][0] * li0, of[n][1] * li0, h2, l2);
        *(uint32_t*)(oh + row0 * Dc + col) = h2;
        *(uint32_t*)(ol + row0 * Dc + col) = l2;
        split_pack2(of[n][2] * li1, of[n][3] * li1, h2, l2);
        *(uint32_t*)(oh + (row0 + 8) * Dc + col) = h2;
        *(uint32_t*)(ol + (row0 + 8) * Dc + col) = l2;
    }
}

// ---------------- launch ----------------------------------------------------
extern "C" void kernel_launch(void* const* d_in, const int* in_sizes, int n_in,
                              void* d_out, int out_size) {
    const int*   ids    = (const int*)  d_in[0];
    const int*   pos    = (const int*)  d_in[1];
    const float* embed  = (const float*)d_in[2];
    const float* Wqkv   = (const float*)d_in[3];
    const float* Wo     = (const float*)d_in[4];
    const float* Wgu    = (const float*)d_in[5];
    const float* Wd     = (const float*)d_in[6];
    const float* ln1    = (const float*)d_in[7];
    const float* ln2    = (const float*)d_in[8];
    const float* norm_w = (const float*)d_in[9];
    const float* lmh    = (const float*)d_in[10];
    float* out = (float*)d_out;

    float *h, *qkv;
    __nv_bfloat16 *xh, *xl, *oh, *ol, *ah, *al;
    __nv_bfloat16 *wqkvh, *wqkvl, *woh, *wol, *wguh, *wgul, *wdh, *wdl, *lmhh, *lmhl;
    cudaGetSymbolAddress((void**)&h,   g_h);
    cudaGetSymbolAddress((void**)&qkv, g_qkv);
    cudaGetSymbolAddress((void**)&xh,  g_xh);  cudaGetSymbolAddress((void**)&xl, g_xl);
    cudaGetSymbolAddress((void**)&oh,  g_oh);  cudaGetSymbolAddress((void**)&ol, g_ol);
    cudaGetSymbolAddress((void**)&ah,  g_ah);  cudaGetSymbolAddress((void**)&al, g_al);
    cudaGetSymbolAddress((void**)&wqkvh, g_wqkvh); cudaGetSymbolAddress((void**)&wqkvl, g_wqkvl);
    cudaGetSymbolAddress((void**)&woh,   g_woh);   cudaGetSymbolAddress((void**)&wol,   g_wol);
    cudaGetSymbolAddress((void**)&wguh,  g_wguh);  cudaGetSymbolAddress((void**)&wgul,  g_wgul);
    cudaGetSymbolAddress((void**)&wdh,   g_wdh);   cudaGetSymbolAddress((void**)&wdl,   g_wdl);
    cudaGetSymbolAddress((void**)&lmhh,  g_lmhh);  cudaGetSymbolAddress((void**)&lmhl,  g_lmhl);

    cudaFuncSetAttribute(attn_kernel,
                         cudaFuncAttributeMaxDynamicSharedMemorySize, ATTN_SMEM);
    cudaFuncSetAttribute(gemm_bf16x3,
                         cudaFuncAttributeMaxDynamicSharedMemorySize, GEMM_SMEM);

    // split all weights into bf16 hi/lo (Wgu gate/up-interleaved)
    {
        const long long n1 = (long long)Lc*QKVc*Dc, n2 = (long long)Lc*Dc*Dc,
                        n3 = (long long)Lc*GUc*Dc,  n4 = (long long)Lc*Dc*Ic,
                        n5 = (long long)Vc*Dc;
        split_kernel<<<(unsigned)((n1/4 + 255)/256), 256>>>(Wqkv, wqkvh, wqkvl, n1);
        split_kernel<<<(unsigned)((n2/4 + 255)/256), 256>>>(Wo,   woh,   wol,   n2);
        split_wgu_kernel<<<(unsigned)((n3/4 + 255)/256), 256>>>(Wgu, wguh, wgul);
        split_kernel<<<(unsigned)((n4/4 + 255)/256), 256>>>(Wd,   wdh,   wdl,   n4);
        split_kernel<<<(unsigned)((n5/4 + 255)/256), 256>>>(lmh,  lmhh,  lmhl,  n5);
    }

    embed_kernel<<<Tc, 128>>>(ids, embed, h);

    for (int l = 0; l < Lc; ++l) {
        rmsnorm_kernel<<<Tc, 256>>>(xh, xl, h, ln1 + (long long)l * Dc);
        gemm_bf16x3<<<dim3(Tc/128, QKVc/128), 128, GEMM_SMEM>>>(
            xh, xl, wqkvh + (long long)l*QKVc*Dc, wqkvl + (long long)l*QKVc*Dc,
            qkv, nullptr, nullptr, Tc, QKVc, Dc, 0);
        rope_kernel<<<(Tc * Hc * 64 + 255) / 256, 256>>>(qkv, pos);
        attn_kernel<<<dim3(Sc / 128, Hc, Bc), 256, ATTN_SMEM>>>(qkv, oh, ol);
        gemm_bf16x3<<<dim3(Tc/128, Dc/128), 128, GEMM_SMEM>>>(
            oh, ol, woh + (long long)l*Dc*Dc, wol + (long long)l*Dc*Dc,
            h, nullptr, nullptr, Tc, Dc, Dc, 1);
        rmsnorm_kernel<<<Tc, 256>>>(xh, xl, h, ln2 + (long long)l * Dc);
        gemm_bf16x3<<<dim3(Tc/128, GUc/128), 128, GEMM_SMEM>>>(
            xh, xl, wguh + (long long)l*GUc*Dc, wgul + (long long)l*GUc*Dc,
            nullptr, ah, al, Tc, GUc, Dc, 2);
        gemm_bf16x3<<<dim3(Tc/128, Dc/128), 128, GEMM_SMEM>>>(
            ah, al, wdh + (long long)l*Dc*Ic, wdl + (long long)l*Dc*Ic,
            h, nullptr, nullptr, Tc, Dc, Ic, 1);
    }

    rmsnorm_kernel<<<Tc, 256>>>(xh, xl, h, norm_w);
    gemm_bf16x3<<<dim3(Tc/128, Vc/128), 128, GEMM_SMEM>>>(
        xh, xl, lmhh, lmhl, out, nullptr, nullptr, Tc, Vc, Dc, 0);
}

// round 15
// speedup vs baseline: 1.0137x; 1.0137x over previous
#include <cuda_runtime.h>
#include <cuda_bf16.h>
#include <cstdint>

// Model dims
#define Lc   4
#define Dc   2048
#define Hc   16
#define HDc  128
#define Ic   5632
#define Vc   32000
#define Bc   2
#define Sc   1024
#define Tc   (Bc*Sc)        // 2048 tokens
#define QKVc (3*Hc*HDc)     // 6144
#define GUc  (2*Ic)         // 11264

// ---------------- scratch (static device globals; no allocations) ----------
__device__ float g_h  [Tc*Dc];     // residual (fp32)
__device__ float g_qkv[Tc*QKVc];   // qkv fp32 (attention input)

// split activations (bf16 hi/lo)
__device__ __nv_bfloat16 g_xh[Tc*Dc],  g_xl[Tc*Dc];
__device__ __nv_bfloat16 g_oh[Tc*Dc],  g_ol[Tc*Dc];
__device__ __nv_bfloat16 g_ah[Tc*Ic],  g_al[Tc*Ic];

// split weights (bf16 hi/lo); Wgu is stored gate/up row-interleaved
__device__ __nv_bfloat16 g_wqkvh[Lc*QKVc*Dc], g_wqkvl[Lc*QKVc*Dc];
__device__ __nv_bfloat16 g_woh  [Lc*Dc*Dc],   g_wol  [Lc*Dc*Dc];
__device__ __nv_bfloat16 g_wguh [Lc*GUc*Dc],  g_wgul [Lc*GUc*Dc];
__device__ __nv_bfloat16 g_wdh  [Lc*Dc*Ic],   g_wdl  [Lc*Dc*Ic];
__device__ __nv_bfloat16 g_lmhh [Vc*Dc],      g_lmhl [Vc*Dc];

// ---------------- small helpers --------------------------------------------
__device__ __forceinline__ uint32_t smem_u32(const void* p) {
    uint32_t a;
    asm("{ .reg .u64 t; cvta.to.shared.u64 t, %1; cvt.u32.u64 %0, t; }"
        : "=r"(a) : "l"(p));
    return a;
}
__device__ __forceinline__ void split_store4(__nv_bfloat16* hp, __nv_bfloat16* lp,
                                             long long off, float4 v) {
    __nv_bfloat16 h0 = __float2bfloat16(v.x), h1 = __float2bfloat16(v.y);
    __nv_bfloat16 h2 = __float2bfloat16(v.z), h3 = __float2bfloat16(v.w);
    __nv_bfloat16 l0 = __float2bfloat16(v.x - __bfloat162float(h0));
    __nv_bfloat16 l1 = __float2bfloat16(v.y - __bfloat162float(h1));
    __nv_bfloat16 l2 = __float2bfloat16(v.z - __bfloat162float(h2));
    __nv_bfloat16 l3 = __float2bfloat16(v.w - __bfloat162float(h3));
    *(ushort4*)(hp + off) = make_ushort4(__bfloat16_as_ushort(h0), __bfloat16_as_ushort(h1),
                                         __bfloat16_as_ushort(h2), __bfloat16_as_ushort(h3));
    *(ushort4*)(lp + off) = make_ushort4(__bfloat16_as_ushort(l0), __bfloat16_as_ushort(l1),
                                         __bfloat16_as_ushort(l2), __bfloat16_as_ushort(l3));
}
__device__ __forceinline__ void split_pack2(float a, float b,
                                            uint32_t& h, uint32_t& l) {
    __nv_bfloat16 ha = __float2bfloat16(a), hb = __float2bfloat16(b);
    __nv_bfloat16 la = __float2bfloat16(a - __bfloat162float(ha));
    __nv_bfloat16 lb = __float2bfloat16(b - __bfloat162float(hb));
    h = (uint32_t)__bfloat16_as_ushort(ha) | ((uint32_t)__bfloat16_as_ushort(hb) << 16);
    l = (uint32_t)__bfloat16_as_ushort(la) | ((uint32_t)__bfloat16_as_ushort(lb) << 16);
}

// ---------------- weight split ---------------------------------------------
__global__ void split_kernel(const float* __restrict__ s,
                             __nv_bfloat16* __restrict__ hp,
                             __nv_bfloat16* __restrict__ lp, long long n) {
    long long i = ((long long)blockIdx.x * blockDim.x + threadIdx.x) * 4;
    if (i >= n) return;
    split_store4(hp, lp, i, *(const float4*)(s + i));
}

// Wgu split with gate/up row interleave: dst row 2j = gate j, 2j+1 = up j.
__global__ void split_wgu_kernel(const float* __restrict__ s,
                                 __nv_bfloat16* __restrict__ hp,
                                 __nv_bfloat16* __restrict__ lp) {
    const long long total = (long long)Lc * GUc * Dc;
    long long i = ((long long)blockIdx.x * blockDim.x + threadIdx.x) * 4;
    if (i >= total) return;
    const long long layer = i / ((long long)GUc * Dc);
    const long long rem   = i - layer * (long long)GUc * Dc;
    const int nr = (int)(rem / Dc);          // interleaved dst row
    const int k  = (int)(rem - (long long)nr * Dc);
    const int sr = (nr & 1) ? (Ic + (nr >> 1)) : (nr >> 1);
    const long long src = layer * (long long)GUc * Dc + (long long)sr * Dc + k;
    split_store4(hp, lp, i, *(const float4*)(s + src));
}

// ---------------- embedding gather -----------------------------------------
__global__ void embed_kernel(const int* __restrict__ ids,
                             const float* __restrict__ emb,
                             float* __restrict__ h) {
    const int t = blockIdx.x;
    const int id = ids[t];
    const float4* src = (const float4*)(emb + (long long)id * Dc);
    float4* dst = (float4*)(h + (long long)t * Dc);
    for (int i = threadIdx.x; i < Dc / 4; i += blockDim.x) dst[i] = src[i];
}

// ---------------- rmsnorm -> split bf16 -------------------------------------
__global__ void __launch_bounds__(256) rmsnorm_kernel(
    __nv_bfloat16* __restrict__ oh, __nv_bfloat16* __restrict__ ol,
    const float* __restrict__ in, const float* __restrict__ w) {
    const int t = blockIdx.x;
    const int tid = threadIdx.x;
    const float4* row = (const float4*)(in + (long long)t * Dc);
    float4 v0 = row[tid];
    float4 v1 = row[tid + 256];
    float ss = v0.x*v0.x + v0.y*v0.y + v0.z*v0.z + v0.w*v0.w
             + v1.x*v1.x + v1.y*v1.y + v1.z*v1.z + v1.w*v1.w;
    #pragma unroll
    for (int m = 16; m >= 1; m >>= 1) ss += __shfl_xor_sync(0xffffffffu, ss, m);
    __shared__ float red[8];
    __shared__ float s_inv;
    if ((tid & 31) == 0) red[tid >> 5] = ss;
    __syncthreads();
    if (tid == 0) {
        float tot = 0.f;
        #pragma unroll
        for (int i = 0; i < 8; ++i) tot += red[i];
        s_inv = rsqrtf(tot * (1.0f / (float)Dc) + 1e-6f);
    }
    __syncthreads();
    const float inv = s_inv;
    const float4* wv = (const float4*)w;
    float4 w0 = wv[tid], w1 = wv[tid + 256];
    float4 o0 = make_float4(v0.x*inv*w0.x, v0.y*inv*w0.y, v0.z*inv*w0.z, v0.w*inv*w0.w);
    float4 o1 = make_float4(v1.x*inv*w1.x, v1.y*inv*w1.y, v1.z*inv*w1.z, v1.w*inv*w1.w);
    const long long base = (long long)t * Dc;
    split_store4(oh, ol, base + tid * 4, o0);
    split_store4(oh, ol, base + (tid + 256) * 4, o1);
}

// ---------------- rope ------------------------------------------------------
__global__ void rope_kernel(float* __restrict__ qkv, const int* __restrict__ pos) {
    const int idx = blockIdx.x * blockDim.x + threadIdx.x;
    if (idx >= Tc * Hc * (HDc / 2)) return;
    const int i  = idx & 63;
    const int hh = (idx >> 6) & (Hc - 1);
    const int t  = idx >> 10;
    const float freq = expf(-(float)i * (9.210340371976184f / 64.0f));
    const float ang  = (float)pos[t & (Sc - 1)] * freq;
    float s, c;
    sincosf(ang, &s, &c);
    const long long base = (long long)t * QKVc + hh * HDc + i;
    float q1 = qkv[base], q2 = qkv[base + 64];
    qkv[base]      = q1 * c - q2 * s;
    qkv[base + 64] = q2 * c + q1 * s;
    const long long kb = base + Dc;
    float k1 = qkv[kb], k2 = qkv[kb + 64];
    qkv[kb]      = k1 * c - k2 * s;
    qkv[kb + 64] = k2 * c + k1 * s;
}

// ---------------- bf16x3 NT GEMM (R13 winner config + fused-silu mode) ------
// 8 warps (2m x 4n), warp tile 64x32, 128x128 CTA tile, BK=32, 2-stage cp.async.
// mode 0: store C; 1: C += ; 2: silu-fused (gate/up interleaved cols) -> Oh/Ol.
#define PITCH       80
#define TILE_BYTES  (128*PITCH)      // 10240
#define STAGE_BYTES (4*TILE_BYTES)   // 40960: Ah, Al, Bh, Bl
#define GEMM_SMEM   (2*STAGE_BYTES)  // 81920 -> 2 CTAs/SM

__device__ __forceinline__ void cp16(uint32_t dst, const void* src) {
    asm volatile("cp.async.cg.shared.global [%0], [%1], 16;" :: "r"(dst), "l"(src));
}
__device__ __forceinline__ void ldsm4(uint32_t* r, uint32_t addr) {
    asm volatile("ldmatrix.sync.aligned.m8n8.x4.shared.b16 {%0,%1,%2,%3}, [%4];"
                 : "=r"(r[0]), "=r"(r[1]), "=r"(r[2]), "=r"(r[3]) : "r"(addr));
}
__device__ __forceinline__ void ldsm2(uint32_t* r, uint32_t addr) {
    asm volatile("ldmatrix.sync.aligned.m8n8.x2.shared.b16 {%0,%1}, [%2];"
                 : "=r"(r[0]), "=r"(r[1]) : "r"(addr));
}
__device__ __forceinline__ void mma_bf16(float* c, const uint32_t* a, const uint32_t* b) {
    asm volatile(
        "mma.sync.aligned.m16n8k16.row.col.f32.bf16.bf16.f32 "
        "{%0,%1,%2,%3}, {%4,%5,%6,%7}, {%8,%9}, {%0,%1,%2,%3};"
        : "+f"(c[0]), "+f"(c[1]), "+f"(c[2]), "+f"(c[3])
        : "r"(a[0]), "r"(a[1]), "r"(a[2]), "r"(a[3]), "r"(b[0]), "r"(b[1]));
}
__device__ __forceinline__ float silu_mul(float g, float u) {
    return (g / (1.f + expf(-g))) * u;
}

__device__ __forceinline__ void load_stage(
    uint32_t sb, int s,
    const __nv_bfloat16* __restrict__ Ah, const __nv_bfloat16* __restrict__ Al,
    const __nv_bfloat16* __restrict__ Bh, const __nv_bfloat16* __restrict__ Bl,
    long long bm, long long bn, long long K, long long k0, int tid) {
    const __nv_bfloat16* gs[4] = {Ah, Al, Bh, Bl};
    #pragma unroll
    for (int t = 0; t < 4; ++t) {
        const long long row0 = (t < 2) ? bm : bn;
        const __nv_bfloat16* g = gs[t];
        #pragma unroll
        for (int u = 0; u < 2; ++u) {
            const int ch = tid + (u << 8);      // 0..511
            const int r = ch >> 2, c = ch & 3;  // row, 16B chunk
            const uint32_t dst = sb + s * STAGE_BYTES + t * TILE_BYTES
                               + r * PITCH + c * 16;
            cp16(dst, g + (row0 + r) * K + k0 + c * 8);
        }
    }
}

__global__ void __launch_bounds__(256) gemm_bf16x3(
    const __nv_bfloat16* __restrict__ Ah, const __nv_bfloat16* __restrict__ Al,
    const __nv_bfloat16* __restrict__ Bh, const __nv_bfloat16* __restrict__ Bl,
    float* __restrict__ C,
    __nv_bfloat16* __restrict__ Oh, __nv_bfloat16* __restrict__ Ol,
    int M, int N, int K, int mode) {
    extern __shared__ char smraw[];
    const uint32_t sb = smem_u32(smraw);
    const int tid  = threadIdx.x;
    const int wid  = tid >> 5;
    const int lane = tid & 31;
    const int grp  = lane >> 2;
    const int qid  = lane & 3;
    const int m_base = (wid >> 2) * 64;
    const int n_base = (wid & 3) * 32;
    const long long bm = (long long)blockIdx.x * 128;
    const long long bn = (long long)blockIdx.y * 128;

    float acc[4][4][4];
    #pragma unroll
    for (int i = 0; i < 4; ++i)
        #pragma unroll
        for (int j = 0; j < 4; ++j)
            #pragma unroll
            for (int r = 0; r < 4; ++r) acc[i][j][r] = 0.f;

    const int nIter = K >> 5;
    load_stage(sb, 0, Ah, Al, Bh, Bl, bm, bn, K, 0, tid);
    asm volatile("cp.async.commit_group;" ::: "memory");

    const int arow = lane & 15, achunk = lane >> 4;
    const int brow = lane & 7,  bchunk = (lane >> 3) & 1;

    for (int it = 0; it < nIter; ++it) {
        const int s = it & 1;
        if (it + 1 < nIter) {
            load_stage(sb, s ^ 1, Ah, Al, Bh, Bl, bm, bn, K,
                       (long long)(it + 1) << 5, tid);
            asm volatile("cp.async.commit_group;" ::: "memory");
            asm volatile("cp.async.wait_group 1;" ::: "memory");
        } else {
            asm volatile("cp.async.wait_group 0;" ::: "memory");
        }
        __syncthreads();

        const uint32_t stb = sb + s * STAGE_BYTES;
        #pragma unroll
        for (int ks = 0; ks < 2; ++ks) {
            uint32_t ah[4][4], al[4][4], bh[4][2], bl[4][2];
            #pragma unroll
            for (int mt = 0; mt < 4; ++mt) {
                const uint32_t ad = stb + (m_base + mt * 16 + arow) * PITCH
                                  + (ks * 2 + achunk) * 16;
                ldsm4(ah[mt], ad);
                ldsm4(al[mt], ad + TILE_BYTES);
            }
            #pragma unroll
            for (int nt = 0; nt < 4; ++nt) {
                const uint32_t bd = stb + 2 * TILE_BYTES
                                  + (n_base + nt * 8 + brow) * PITCH
                                  + (ks * 2 + bchunk) * 16;
                ldsm2(bh[nt], bd);
                ldsm2(bl[nt], bd + TILE_BYTES);
            }
            #pragma unroll
            for (int mt = 0; mt < 4; ++mt)
                #pragma unroll
                for (int nt = 0; nt < 4; ++nt) {
                    mma_bf16(acc[mt][nt], ah[mt], bh[nt]);
                    mma_bf16(acc[mt][nt], ah[mt], bl[nt]);
                    mma_bf16(acc[mt][nt], al[mt], bh[nt]);
                }
        }
        __syncthreads();
    }

    if (mode == 2) {
        // silu-fused: even col = gate, odd col = up; output width N/2
        const int NO = N >> 1;
        #pragma unroll
        for (int mt = 0; mt < 4; ++mt) {
            #pragma unroll
            for (int nt = 0; nt < 4; ++nt) {
                const long long row = bm + m_base + mt * 16 + grp;
                const long long col = (bn + n_base + nt * 8 + 2 * qid) >> 1;
                float* c = acc[mt][nt];
                const float a0 = silu_mul(c[0], c[1]);
                const float a1 = silu_mul(c[2], c[3]);
                __nv_bfloat16 h0 = __float2bfloat16(a0);
                __nv_bfloat16 l0 = __float2bfloat16(a0 - __bfloat162float(h0));
                __nv_bfloat16 h1 = __float2bfloat16(a1);
                __nv_bfloat16 l1 = __float2bfloat16(a1 - __bfloat162float(h1));
                Oh[row * NO + col] = h0;  Ol[row * NO + col] = l0;
                Oh[(row + 8) * NO + col] = h1;  Ol[(row + 8) * NO + col] = l1;
            }
        }
        return;
    }

    #pragma unroll
    for (int mt = 0; mt < 4; ++mt) {
        #pragma unroll
        for (int nt = 0; nt < 4; ++nt) {
            const long long row = bm + m_base + mt * 16 + grp;
            const long long col = bn + n_base + nt * 8 + 2 * qid;
            float* c = acc[mt][nt];
            if (mode == 1) {
                float2 r0 = *(const float2*)&C[row * N + col];
                float2 r1 = *(const float2*)&C[(row + 8) * N + col];
                c[0] += r0.x; c[1] += r0.y; c[2] += r1.x; c[3] += r1.y;
            }
            *(float2*)&C[row * N + col]       = make_float2(c[0], c[1]);
            *(float2*)&C[(row + 8) * N + col] = make_float2(c[2], c[3]);
        }
    }
}

// ---------------- tensor-core flash attention (bf16x3) ----------------------
#define AQP 272   // Q row pitch: 128 bf16 = 256B + 16 pad
#define AKP 272   // K row pitch
#define AVP 144   // V^T row pitch: 64 bf16 = 128B + 16 pad
#define OFF_QH 0
#define OFF_QL (128*AQP)
#define OFF_KH (2*128*AQP)
#define OFF_KL (OFF_KH + 64*AKP)
#define OFF_VH (OFF_KL + 64*AKP)
#define OFF_VL (OFF_VH + 128*AVP)
#define ATTN_SMEM (OFF_VL + 128*AVP)   // 141312 bytes

__global__ void __launch_bounds__(256) attn_kernel(
    const float* __restrict__ qkv,
    __nv_bfloat16* __restrict__ oh, __nv_bfloat16* __restrict__ ol) {
    extern __shared__ char sm[];
    const uint32_t sb = smem_u32(sm);
    const int tid = threadIdx.x, wid = tid >> 5, lane = tid & 31;
    const int grp = lane >> 2, qid = lane & 3;
    const int qt = (int)gridDim.x - 1 - (int)blockIdx.x;  // heavy first
    const int hh = blockIdx.y, b = blockIdx.z;
    const int q0 = qt * 128;
    const int tok0 = b * Sc + q0;
    const float scale = 0.08838834764831845f;

    for (int idx = tid; idx < 128 * 128; idx += 256) {
        const int r = idx >> 7, d = idx & 127;
        const float v = qkv[(long long)(tok0 + r) * QKVc + hh * HDc + d] * scale;
        const __nv_bfloat16 h = __float2bfloat16(v);
        const __nv_bfloat16 l = __float2bfloat16(v - __bfloat162float(h));
        *(unsigned short*)(sm + OFF_QH + r * AQP + d * 2) = __bfloat16_as_ushort(h);
        *(unsigned short*)(sm + OFF_QL + r * AQP + d * 2) = __bfloat16_as_ushort(l);
    }

    float of[16][4];
    #pragma unroll
    for (int n = 0; n < 16; ++n)
        #pragma unroll
        for (int r = 0; r < 4; ++r) of[n][r] = 0.f;
    float m0 = -3.0e38f, m1 = -3.0e38f, l0 = 0.f, l1 = 0.f;

    const int arow = lane & 15, achunk = lane >> 4;
    const int brow = lane & 7,  bchunk = (lane >> 3) & 1;
    const int rb = q0 + wid * 16;
    const int n_tiles = (q0 >> 6) + 2;

    for (int kt = 0; kt < n_tiles; ++kt) {
        __syncthreads();
        const int ktok = b * Sc + kt * 64;
        for (int idx = tid; idx < 64 * 128; idx += 256) {
            const int r = idx >> 7, d = idx & 127;
            const long long gk = (long long)(ktok + r) * QKVc + Dc + hh * HDc + d;
            const float kv = qkv[gk];
            __nv_bfloat16 h = __float2bfloat16(kv);
            __nv_bfloat16 l = __float2bfloat16(kv - __bfloat162float(h));
            *(unsigned short*)(sm + OFF_KH + r * AKP + d * 2) = __bfloat16_as_ushort(h);
            *(unsigned short*)(sm + OFF_KL + r * AKP + d * 2) = __bfloat16_as_ushort(l);
            const float vv = qkv[gk + Dc];
            h = __float2bfloat16(vv);
            l = __float2bfloat16(vv - __bfloat162float(h));
            *(unsigned short*)(sm + OFF_VH + d * AVP + r * 2) = __bfloat16_as_ushort(h);
            *(unsigned short*)(sm + OFF_VL + d * AVP + r * 2) = __bfloat16_as_ushort(l);
        }
        __syncthreads();

        float sfr[8][4];
        #pragma unroll
        for (int j = 0; j < 8; ++j)
            #pragma unroll
            for (int r = 0; r < 4; ++r) sfr[j][r] = 0.f;
        #pragma unroll
        for (int ks = 0; ks < 8; ++ks) {
            uint32_t qh[4], ql[4];
            const uint32_t qa = sb + OFF_QH + (wid * 16 + arow) * AQP + (ks * 2 + achunk) * 16;
            ldsm4(qh, qa);
            ldsm4(ql, qa + (OFF_QL - OFF_QH));
            #pragma unroll
            for (int j = 0; j < 8; ++j) {
                uint32_t kh2[2], kl2[2];
                const uint32_t ka = sb + OFF_KH + (8 * j + brow) * AKP + (ks * 2 + bchunk) * 16;
                ldsm2(kh2, ka);
                ldsm2(kl2, ka + (OFF_KL - OFF_KH));
                mma_bf16(sfr[j], qh, kh2);
                mma_bf16(sfr[j], qh, kl2);
                mma_bf16(sfr[j], ql, kh2);
            }
        }

        if (kt * 64 + 63 > rb) {
            #pragma unroll
            for (int j = 0; j < 8; ++j) {
                const int col = kt * 64 + 8 * j + 2 * qid;
                const int r0g = rb + grp, r1g = rb + grp + 8;
                if (col     > r0g) sfr[j][0] = -3.0e38f;
                if (col + 1 > r0g) sfr[j][1] = -3.0e38f;
                if (col     > r1g) sfr[j][2] = -3.0e38f;
                if (col + 1 > r1g) sfr[j][3] = -3.0e38f;
            }
        }

        float ml0 = -3.0e38f, ml1 = -3.0e38f;
        #pragma unroll
        for (int j = 0; j < 8; ++j) {
            ml0 = fmaxf(ml0, fmaxf(sfr[j][0], sfr[j][1]));
            ml1 = fmaxf(ml1, fmaxf(sfr[j][2], sfr[j][3]));
        }
        ml0 = fmaxf(ml0, __shfl_xor_sync(0xffffffffu, ml0, 1));
        ml0 = fmaxf(ml0, __shfl_xor_sync(0xffffffffu, ml0, 2));
        ml1 = fmaxf(ml1, __shfl_xor_sync(0xffffffffu, ml1, 1));
        ml1 = fmaxf(ml1, __shfl_xor_sync(0xffffffffu, ml1, 2));
        const float mn0 = fmaxf(m0, ml0), mn1 = fmaxf(m1, ml1);
        const float sc0 = expf(m0 - mn0), sc1 = expf(m1 - mn1);
        m0 = mn0; m1 = mn1;

        float rs0 = 0.f, rs1 = 0.f;
        uint32_t pah[4][4], pal[4][4];
        #pragma unroll
        for (int t = 0; t < 4; ++t) {
            const float p00 = expf(sfr[2*t][0] - mn0), p01 = expf(sfr[2*t][1] - mn0);
            const float p02 = expf(sfr[2*t][2] - mn1), p03 = expf(sfr[2*t][3] - mn1);
            const float p10 = expf(sfr[2*t+1][0] - mn0), p11 = expf(sfr[2*t+1][1] - mn0);
            const float p12 = expf(sfr[2*t+1][2] - mn1), p13 = expf(sfr[2*t+1][3] - mn1);
            rs0 += p00 + p01 + p10 + p11;
            rs1 += p02 + p03 + p12 + p13;
            split_pack2(p00, p01, pah[t][0], pal[t][0]);
            split_pack2(p02, p03, pah[t][1], pal[t][1]);
            split_pack2(p10, p11, pah[t][2], pal[t][2]);
            split_pack2(p12, p13, pah[t][3], pal[t][3]);
        }
        rs0 += __shfl_xor_sync(0xffffffffu, rs0, 1);
        rs0 += __shfl_xor_sync(0xffffffffu, rs0, 2);
        rs1 += __shfl_xor_sync(0xffffffffu, rs1, 1);
        rs1 += __shfl_xor_sync(0xffffffffu, rs1, 2);
        l0 = l0 * sc0 + rs0;
        l1 = l1 * sc1 + rs1;

        #pragma unroll
        for (int n = 0; n < 16; ++n) {
            of[n][0] *= sc0; of[n][1] *= sc0;
            of[n][2] *= sc1; of[n][3] *= sc1;
        }
        #pragma unroll
        for (int t = 0; t < 4; ++t) {
            #pragma unroll
            for (int n = 0; n < 16; ++n) {
                uint32_t vh2[2], vl2[2];
                const uint32_t va = sb + OFF_VH + (8 * n + brow) * AVP + (t * 2 + bchunk) * 16;
                ldsm2(vh2, va);
                ldsm2(vl2, va + (OFF_VL - OFF_VH));
                mma_bf16(of[n], pah[t], vh2);
                mma_bf16(of[n], pah[t], vl2);
                mma_bf16(of[n], pal[t], vh2);
            }
        }
    }

    const float li0 = 1.f / l0, li1 = 1.f / l1;
    const long long row0 = (long long)(tok0 + wid * 16 + grp);
    #pragma unroll
    for (int n = 0; n < 16; ++n) {
        const long long col = hh * HDc + 8 * n + 2 * qid;
        uint32_t h2, l2;
        split_pack2(of[n][0] * li0, of[n][1] * li0, h2, l2);
        *(uint32_t*)(oh + row0 * Dc + col) = h2;
        *(uint32_t*)(ol + row0 * Dc + col) = l2;
        split_pack2(of[n][2] * li1, of[n][3] * li1, h2, l2);
        *(uint32_t*)(oh + (row0 + 8) * Dc + col) = h2;
        *(uint32_t*)(ol + (row0 + 8) * Dc + col) = l2;
    }
}

// ---------------- launch ----------------------------------------------------
extern "C" void kernel_launch(void* const* d_in, const int* in_sizes, int n_in,
                              void* d_out, int out_size) {
    const int*   ids    = (const int*)  d_in[0];
    const int*   pos    = (const int*)  d_in[1];
    const float* embed  = (const float*)d_in[2];
    const float* Wqkv   = (const float*)d_in[3];
    const float* Wo     = (const float*)d_in[4];
    const float* Wgu    = (const float*)d_in[5];
    const float* Wd     = (const float*)d_in[6];
    const float* ln1    = (const float*)d_in[7];
    const float* ln2    = (const float*)d_in[8];
    const float* norm_w = (const float*)d_in[9];
    const float* lmh    = (const float*)d_in[10];
    float* out = (float*)d_out;

    float *h, *qkv;
    __nv_bfloat16 *xh, *xl, *oh, *ol, *ah, *al;
    __nv_bfloat16 *wqkvh, *wqkvl, *woh, *wol, *wguh, *wgul, *wdh, *wdl, *lmhh, *lmhl;
    cudaGetSymbolAddress((void**)&h,   g_h);
    cudaGetSymbolAddress((void**)&qkv, g_qkv);
    cudaGetSymbolAddress((void**)&xh,  g_xh);  cudaGetSymbolAddress((void**)&xl, g_xl);
    cudaGetSymbolAddress((void**)&oh,  g_oh);  cudaGetSymbolAddress((void**)&ol, g_ol);
    cudaGetSymbolAddress((void**)&ah,  g_ah);  cudaGetSymbolAddress((void**)&al, g_al);
    cudaGetSymbolAddress((void**)&wqkvh, g_wqkvh); cudaGetSymbolAddress((void**)&wqkvl, g_wqkvl);
    cudaGetSymbolAddress((void**)&woh,   g_woh);   cudaGetSymbolAddress((void**)&wol,   g_wol);
    cudaGetSymbolAddress((void**)&wguh,  g_wguh);  cudaGetSymbolAddress((void**)&wgul,  g_wgul);
    cudaGetSymbolAddress((void**)&wdh,   g_wdh);   cudaGetSymbolAddress((void**)&wdl,   g_wdl);
    cudaGetSymbolAddress((void**)&lmhh,  g_lmhh);  cudaGetSymbolAddress((void**)&lmhl,  g_lmhl);

    cudaFuncSetAttribute(attn_kernel,
                         cudaFuncAttributeMaxDynamicSharedMemorySize, ATTN_SMEM);
    cudaFuncSetAttribute(gemm_bf16x3,
                         cudaFuncAttributeMaxDynamicSharedMemorySize, GEMM_SMEM);

    // split all weights into bf16 hi/lo (Wgu gate/up-interleaved)
    {
        const long long n1 = (long long)Lc*QKVc*Dc, n2 = (long long)Lc*Dc*Dc,
                        n3 = (long long)Lc*GUc*Dc,  n4 = (long long)Lc*Dc*Ic,
                        n5 = (long long)Vc*Dc;
        split_kernel<<<(unsigned)((n1/4 + 255)/256), 256>>>(Wqkv, wqkvh, wqkvl, n1);
        split_kernel<<<(unsigned)((n2/4 + 255)/256), 256>>>(Wo,   woh,   wol,   n2);
        split_wgu_kernel<<<(unsigned)((n3/4 + 255)/256), 256>>>(Wgu, wguh, wgul);
        split_kernel<<<(unsigned)((n4/4 + 255)/256), 256>>>(Wd,   wdh,   wdl,   n4);
        split_kernel<<<(unsigned)((n5/4 + 255)/256), 256>>>(lmh,  lmhh,  lmhl,  n5);
    }

    embed_kernel<<<Tc, 128>>>(ids, embed, h);

    for (int l = 0; l < Lc; ++l) {
        rmsnorm_kernel<<<Tc, 256>>>(xh, xl, h, ln1 + (long long)l * Dc);
        gemm_bf16x3<<<dim3(Tc/128, QKVc/128), 256, GEMM_SMEM>>>(
            xh, xl, wqkvh + (long long)l*QKVc*Dc, wqkvl + (long long)l*QKVc*Dc,
            qkv, nullptr, nullptr, Tc, QKVc, Dc, 0);
        rope_kernel<<<(Tc * Hc * 64 + 255) / 256, 256>>>(qkv, pos);
        attn_kernel<<<dim3(Sc / 128, Hc, Bc), 256, ATTN_SMEM>>>(qkv, oh, ol);
        gemm_bf16x3<<<dim3(Tc/128, Dc/128), 256, GEMM_SMEM>>>(
            oh, ol, woh + (long long)l*Dc*Dc, wol + (long long)l*Dc*Dc,
            h, nullptr, nullptr, Tc, Dc, Dc, 1);
        rmsnorm_kernel<<<Tc, 256>>>(xh, xl, h, ln2 + (long long)l * Dc);
        gemm_bf16x3<<<dim3(Tc/128, GUc/128), 256, GEMM_SMEM>>>(
            xh, xl, wguh + (long long)l*GUc*Dc, wgul + (long long)l*GUc*Dc,
            nullptr, ah, al, Tc, GUc, Dc, 2);
        gemm_bf16x3<<<dim3(Tc/128, Dc/128), 256, GEMM_SMEM>>>(
            ah, al, wdh + (long long)l*Dc*Ic, wdl + (long long)l*Dc*Ic,
            h, nullptr, nullptr, Tc, Dc, Ic, 1);
    }

    rmsnorm_kernel<<<Tc, 256>>>(xh, xl, h, norm_w);
    gemm_bf16x3<<<dim3(Tc/128, Vc/128), 256, GEMM_SMEM>>>(
        xh, xl, lmhh, lmhl, out, nullptr, nullptr, Tc, Vc, Dc, 0);
}

// round 16
// speedup vs baseline: 1.0152x; 1.0015x over previous
#include <cuda_runtime.h>
#include <cuda_bf16.h>
#include <cstdint>

// Model dims
#define Lc   4
#define Dc   2048
#define Hc   16
#define HDc  128
#define Ic   5632
#define Vc   32000
#define Bc   2
#define Sc   1024
#define Tc   (Bc*Sc)        // 2048 tokens
#define QKVc (3*Hc*HDc)     // 6144
#define GUc  (2*Ic)         // 11264

// ---------------- scratch (static device globals; no allocations) ----------
__device__ float g_h  [Tc*Dc];     // residual (fp32)
__device__ float g_qkv[Tc*QKVc];   // qkv fp32 (attention input)

// split activations (bf16 hi/lo)
__device__ __nv_bfloat16 g_xh[Tc*Dc],  g_xl[Tc*Dc];
__device__ __nv_bfloat16 g_oh[Tc*Dc],  g_ol[Tc*Dc];
__device__ __nv_bfloat16 g_ah[Tc*Ic],  g_al[Tc*Ic];

// split weights (bf16 hi/lo); Wgu is stored gate/up row-interleaved
__device__ __nv_bfloat16 g_wqkvh[Lc*QKVc*Dc], g_wqkvl[Lc*QKVc*Dc];
__device__ __nv_bfloat16 g_woh  [Lc*Dc*Dc],   g_wol  [Lc*Dc*Dc];
__device__ __nv_bfloat16 g_wguh [Lc*GUc*Dc],  g_wgul [Lc*GUc*Dc];
__device__ __nv_bfloat16 g_wdh  [Lc*Dc*Ic],   g_wdl  [Lc*Dc*Ic];
__device__ __nv_bfloat16 g_lmhh [Vc*Dc],      g_lmhl [Vc*Dc];

// ---------------- small helpers --------------------------------------------
__device__ __forceinline__ uint32_t smem_u32(const void* p) {
    uint32_t a;
    asm("{ .reg .u64 t; cvta.to.shared.u64 t, %1; cvt.u32.u64 %0, t; }"
        : "=r"(a) : "l"(p));
    return a;
}
__device__ __forceinline__ void split_store4(__nv_bfloat16* hp, __nv_bfloat16* lp,
                                             long long off, float4 v) {
    __nv_bfloat16 h0 = __float2bfloat16(v.x), h1 = __float2bfloat16(v.y);
    __nv_bfloat16 h2 = __float2bfloat16(v.z), h3 = __float2bfloat16(v.w);
    __nv_bfloat16 l0 = __float2bfloat16(v.x - __bfloat162float(h0));
    __nv_bfloat16 l1 = __float2bfloat16(v.y - __bfloat162float(h1));
    __nv_bfloat16 l2 = __float2bfloat16(v.z - __bfloat162float(h2));
    __nv_bfloat16 l3 = __float2bfloat16(v.w - __bfloat162float(h3));
    *(ushort4*)(hp + off) = make_ushort4(__bfloat16_as_ushort(h0), __bfloat16_as_ushort(h1),
                                         __bfloat16_as_ushort(h2), __bfloat16_as_ushort(h3));
    *(ushort4*)(lp + off) = make_ushort4(__bfloat16_as_ushort(l0), __bfloat16_as_ushort(l1),
                                         __bfloat16_as_ushort(l2), __bfloat16_as_ushort(l3));
}
__device__ __forceinline__ void split_pack2(float a, float b,
                                            uint32_t& h, uint32_t& l) {
    __nv_bfloat16 ha = __float2bfloat16(a), hb = __float2bfloat16(b);
    __nv_bfloat16 la = __float2bfloat16(a - __bfloat162float(ha));
    __nv_bfloat16 lb = __float2bfloat16(b - __bfloat162float(hb));
    h = (uint32_t)__bfloat16_as_ushort(ha) | ((uint32_t)__bfloat16_as_ushort(hb) << 16);
    l = (uint32_t)__bfloat16_as_ushort(la) | ((uint32_t)__bfloat16_as_ushort(lb) << 16);
}

// ---------------- weight split ---------------------------------------------
__global__ void split_kernel(const float* __restrict__ s,
                             __nv_bfloat16* __restrict__ hp,
                             __nv_bfloat16* __restrict__ lp, long long n) {
    long long i = ((long long)blockIdx.x * blockDim.x + threadIdx.x) * 4;
    if (i >= n) return;
    split_store4(hp, lp, i, *(const float4*)(s + i));
}

// Wgu split with gate/up row interleave: dst row 2j = gate j, 2j+1 = up j.
__global__ void split_wgu_kernel(const float* __restrict__ s,
                                 __nv_bfloat16* __restrict__ hp,
                                 __nv_bfloat16* __restrict__ lp) {
    const long long total = (long long)Lc * GUc * Dc;
    long long i = ((long long)blockIdx.x * blockDim.x + threadIdx.x) * 4;
    if (i >= total) return;
    const long long layer = i / ((long long)GUc * Dc);
    const long long rem   = i - layer * (long long)GUc * Dc;
    const int nr = (int)(rem / Dc);          // interleaved dst row
    const int k  = (int)(rem - (long long)nr * Dc);
    const int sr = (nr & 1) ? (Ic + (nr >> 1)) : (nr >> 1);
    const long long src = layer * (long long)GUc * Dc + (long long)sr * Dc + k;
    split_store4(hp, lp, i, *(const float4*)(s + src));
}

// ---------------- embedding gather -----------------------------------------
__global__ void embed_kernel(const int* __restrict__ ids,
                             const float* __restrict__ emb,
                             float* __restrict__ h) {
    const int t = blockIdx.x;
    const int id = ids[t];
    const float4* src = (const float4*)(emb + (long long)id * Dc);
    float4* dst = (float4*)(h + (long long)t * Dc);
    for (int i = threadIdx.x; i < Dc / 4; i += blockDim.x) dst[i] = src[i];
}

// ---------------- rmsnorm -> split bf16 -------------------------------------
__global__ void __launch_bounds__(256) rmsnorm_kernel(
    __nv_bfloat16* __restrict__ oh, __nv_bfloat16* __restrict__ ol,
    const float* __restrict__ in, const float* __restrict__ w) {
    const int t = blockIdx.x;
    const int tid = threadIdx.x;
    const float4* row = (const float4*)(in + (long long)t * Dc);
    float4 v0 = row[tid];
    float4 v1 = row[tid + 256];
    float ss = v0.x*v0.x + v0.y*v0.y + v0.z*v0.z + v0.w*v0.w
             + v1.x*v1.x + v1.y*v1.y + v1.z*v1.z + v1.w*v1.w;
    #pragma unroll
    for (int m = 16; m >= 1; m >>= 1) ss += __shfl_xor_sync(0xffffffffu, ss, m);
    __shared__ float red[8];
    __shared__ float s_inv;
    if ((tid & 31) == 0) red[tid >> 5] = ss;
    __syncthreads();
    if (tid == 0) {
        float tot = 0.f;
        #pragma unroll
        for (int i = 0; i < 8; ++i) tot += red[i];
        s_inv = rsqrtf(tot * (1.0f / (float)Dc) + 1e-6f);
    }
    __syncthreads();
    const float inv = s_inv;
    const float4* wv = (const float4*)w;
    float4 w0 = wv[tid], w1 = wv[tid + 256];
    float4 o0 = make_float4(v0.x*inv*w0.x, v0.y*inv*w0.y, v0.z*inv*w0.z, v0.w*inv*w0.w);
    float4 o1 = make_float4(v1.x*inv*w1.x, v1.y*inv*w1.y, v1.z*inv*w1.z, v1.w*inv*w1.w);
    const long long base = (long long)t * Dc;
    split_store4(oh, ol, base + tid * 4, o0);
    split_store4(oh, ol, base + (tid + 256) * 4, o1);
}

// ---------------- rope ------------------------------------------------------
__global__ void rope_kernel(float* __restrict__ qkv, const int* __restrict__ pos) {
    const int idx = blockIdx.x * blockDim.x + threadIdx.x;
    if (idx >= Tc * Hc * (HDc / 2)) return;
    const int i  = idx & 63;
    const int hh = (idx >> 6) & (Hc - 1);
    const int t  = idx >> 10;
    const float freq = expf(-(float)i * (9.210340371976184f / 64.0f));
    const float ang  = (float)pos[t & (Sc - 1)] * freq;
    float s, c;
    sincosf(ang, &s, &c);
    const long long base = (long long)t * QKVc + hh * HDc + i;
    float q1 = qkv[base], q2 = qkv[base + 64];
    qkv[base]      = q1 * c - q2 * s;
    qkv[base + 64] = q2 * c + q1 * s;
    const long long kb = base + Dc;
    float k1 = qkv[kb], k2 = qkv[kb + 64];
    qkv[kb]      = k1 * c - k2 * s;
    qkv[kb + 64] = k2 * c + k1 * s;
}

// ---------------- bf16x3 NT GEMM (single-sync double-buffer main loop) ------
// 8 warps (2m x 4n), warp tile 64x32, 128x128 CTA tile, BK=32, 2-stage cp.async.
// mode 0: store C; 1: C += ; 2: silu-fused (gate/up interleaved cols) -> Oh/Ol.
#define PITCH       80
#define TILE_BYTES  (128*PITCH)      // 10240
#define STAGE_BYTES (4*TILE_BYTES)   // 40960: Ah, Al, Bh, Bl
#define GEMM_SMEM   (2*STAGE_BYTES)  // 81920 -> 2 CTAs/SM

__device__ __forceinline__ void cp16(uint32_t dst, const void* src) {
    asm volatile("cp.async.cg.shared.global [%0], [%1], 16;" :: "r"(dst), "l"(src));
}
__device__ __forceinline__ void ldsm4(uint32_t* r, uint32_t addr) {
    asm volatile("ldmatrix.sync.aligned.m8n8.x4.shared.b16 {%0,%1,%2,%3}, [%4];"
                 : "=r"(r[0]), "=r"(r[1]), "=r"(r[2]), "=r"(r[3]) : "r"(addr));
}
__device__ __forceinline__ void ldsm2(uint32_t* r, uint32_t addr) {
    asm volatile("ldmatrix.sync.aligned.m8n8.x2.shared.b16 {%0,%1}, [%2];"
                 : "=r"(r[0]), "=r"(r[1]) : "r"(addr));
}
__device__ __forceinline__ void mma_bf16(float* c, const uint32_t* a, const uint32_t* b) {
    asm volatile(
        "mma.sync.aligned.m16n8k16.row.col.f32.bf16.bf16.f32 "
        "{%0,%1,%2,%3}, {%4,%5,%6,%7}, {%8,%9}, {%0,%1,%2,%3};"
        : "+f"(c[0]), "+f"(c[1]), "+f"(c[2]), "+f"(c[3])
        : "r"(a[0]), "r"(a[1]), "r"(a[2]), "r"(a[3]), "r"(b[0]), "r"(b[1]));
}
__device__ __forceinline__ float silu_mul(float g, float u) {
    return (g / (1.f + expf(-g))) * u;
}

__device__ __forceinline__ void load_stage(
    uint32_t sb, int s,
    const __nv_bfloat16* __restrict__ Ah, const __nv_bfloat16* __restrict__ Al,
    const __nv_bfloat16* __restrict__ Bh, const __nv_bfloat16* __restrict__ Bl,
    long long bm, long long bn, long long K, long long k0, int tid) {
    const __nv_bfloat16* gs[4] = {Ah, Al, Bh, Bl};
    #pragma unroll
    for (int t = 0; t < 4; ++t) {
        const long long row0 = (t < 2) ? bm : bn;
        const __nv_bfloat16* g = gs[t];
        #pragma unroll
        for (int u = 0; u < 2; ++u) {
            const int ch = tid + (u << 8);      // 0..511
            const int r = ch >> 2, c = ch & 3;  // row, 16B chunk
            const uint32_t dst = sb + s * STAGE_BYTES + t * TILE_BYTES
                               + r * PITCH + c * 16;
            cp16(dst, g + (row0 + r) * K + k0 + c * 8);
        }
    }
}

__global__ void __launch_bounds__(256) gemm_bf16x3(
    const __nv_bfloat16* __restrict__ Ah, const __nv_bfloat16* __restrict__ Al,
    const __nv_bfloat16* __restrict__ Bh, const __nv_bfloat16* __restrict__ Bl,
    float* __restrict__ C,
    __nv_bfloat16* __restrict__ Oh, __nv_bfloat16* __restrict__ Ol,
    int M, int N, int K, int mode) {
    extern __shared__ char smraw[];
    const uint32_t sb = smem_u32(smraw);
    const int tid  = threadIdx.x;
    const int wid  = tid >> 5;
    const int lane = tid & 31;
    const int grp  = lane >> 2;
    const int qid  = lane & 3;
    const int m_base = (wid >> 2) * 64;
    const int n_base = (wid & 3) * 32;
    const long long bm = (long long)blockIdx.x * 128;
    const long long bn = (long long)blockIdx.y * 128;

    float acc[4][4][4];
    #pragma unroll
    for (int i = 0; i < 4; ++i)
        #pragma unroll
        for (int j = 0; j < 4; ++j)
            #pragma unroll
            for (int r = 0; r < 4; ++r) acc[i][j][r] = 0.f;

    const int nIter = K >> 5;
    load_stage(sb, 0, Ah, Al, Bh, Bl, bm, bn, K, 0, tid);
    asm volatile("cp.async.commit_group;" ::: "memory");

    const int arow = lane & 15, achunk = lane >> 4;
    const int brow = lane & 7,  bchunk = (lane >> 3) & 1;

    for (int it = 0; it < nIter; ++it) {
        const int s = it & 1;
        // stage s data arrived (own groups) ...
        asm volatile("cp.async.wait_group 0;" ::: "memory");
        // ... and all warps finished computing stage s^1 last iter:
        // safe to publish s and overwrite s^1 with next prefetch.
        __syncthreads();
        if (it + 1 < nIter) {
            load_stage(sb, s ^ 1, Ah, Al, Bh, Bl, bm, bn, K,
                       (long long)(it + 1) << 5, tid);
            asm volatile("cp.async.commit_group;" ::: "memory");
        }

        const uint32_t stb = sb + s * STAGE_BYTES;
        #pragma unroll
        for (int ks = 0; ks < 2; ++ks) {
            uint32_t ah[4][4], al[4][4], bh[4][2], bl[4][2];
            #pragma unroll
            for (int mt = 0; mt < 4; ++mt) {
                const uint32_t ad = stb + (m_base + mt * 16 + arow) * PITCH
                                  + (ks * 2 + achunk) * 16;
                ldsm4(ah[mt], ad);
                ldsm4(al[mt], ad + TILE_BYTES);
            }
            #pragma unroll
            for (int nt = 0; nt < 4; ++nt) {
                const uint32_t bd = stb + 2 * TILE_BYTES
                                  + (n_base + nt * 8 + brow) * PITCH
                                  + (ks * 2 + bchunk) * 16;
                ldsm2(bh[nt], bd);
                ldsm2(bl[nt], bd + TILE_BYTES);
            }
            #pragma unroll
            for (int mt = 0; mt < 4; ++mt)
                #pragma unroll
                for (int nt = 0; nt < 4; ++nt) {
                    mma_bf16(acc[mt][nt], ah[mt], bh[nt]);
                    mma_bf16(acc[mt][nt], ah[mt], bl[nt]);
                    mma_bf16(acc[mt][nt], al[mt], bh[nt]);
                }
        }
    }

    if (mode == 2) {
        // silu-fused: even col = gate, odd col = up; output width N/2
        const int NO = N >> 1;
        #pragma unroll
        for (int mt = 0; mt < 4; ++mt) {
            #pragma unroll
            for (int nt = 0; nt < 4; ++nt) {
                const long long row = bm + m_base + mt * 16 + grp;
                const long long col = (bn + n_base + nt * 8 + 2 * qid) >> 1;
                float* c = acc[mt][nt];
                const float a0 = silu_mul(c[0], c[1]);
                const float a1 = silu_mul(c[2], c[3]);
                __nv_bfloat16 h0 = __float2bfloat16(a0);
                __nv_bfloat16 l0 = __float2bfloat16(a0 - __bfloat162float(h0));
                __nv_bfloat16 h1 = __float2bfloat16(a1);
                __nv_bfloat16 l1 = __float2bfloat16(a1 - __bfloat162float(h1));
                Oh[row * NO + col] = h0;  Ol[row * NO + col] = l0;
                Oh[(row + 8) * NO + col] = h1;  Ol[(row + 8) * NO + col] = l1;
            }
        }
        return;
    }

    #pragma unroll
    for (int mt = 0; mt < 4; ++mt) {
        #pragma unroll
        for (int nt = 0; nt < 4; ++nt) {
            const long long row = bm + m_base + mt * 16 + grp;
            const long long col = bn + n_base + nt * 8 + 2 * qid;
            float* c = acc[mt][nt];
            if (mode == 1) {
                float2 r0 = *(const float2*)&C[row * N + col];
                float2 r1 = *(const float2*)&C[(row + 8) * N + col];
                c[0] += r0.x; c[1] += r0.y; c[2] += r1.x; c[3] += r1.y;
            }
            *(float2*)&C[row * N + col]       = make_float2(c[0], c[1]);
            *(float2*)&C[(row + 8) * N + col] = make_float2(c[2], c[3]);
        }
    }
}

// ---------------- tensor-core flash attention (bf16x3) ----------------------
#define AQP 272   // Q row pitch: 128 bf16 = 256B + 16 pad
#define AKP 272   // K row pitch
#define AVP 144   // V^T row pitch: 64 bf16 = 128B + 16 pad
#define OFF_QH 0
#define OFF_QL (128*AQP)
#define OFF_KH (2*128*AQP)
#define OFF_KL (OFF_KH + 64*AKP)
#define OFF_VH (OFF_KL + 64*AKP)
#define OFF_VL (OFF_VH + 128*AVP)
#define ATTN_SMEM (OFF_VL + 128*AVP)   // 141312 bytes

__global__ void __launch_bounds__(256) attn_kernel(
    const float* __restrict__ qkv,
    __nv_bfloat16* __restrict__ oh, __nv_bfloat16* __restrict__ ol) {
    extern __shared__ char sm[];
    const uint32_t sb = smem_u32(sm);
    const int tid = threadIdx.x, wid = tid >> 5, lane = tid & 31;
    const int grp = lane >> 2, qid = lane & 3;
    const int qt = (int)gridDim.x - 1 - (int)blockIdx.x;  // heavy first
    const int hh = blockIdx.y, b = blockIdx.z;
    const int q0 = qt * 128;
    const int tok0 = b * Sc + q0;
    const float scale = 0.08838834764831845f;

    for (int idx = tid; idx < 128 * 128; idx += 256) {
        const int r = idx >> 7, d = idx & 127;
        const float v = qkv[(long long)(tok0 + r) * QKVc + hh * HDc + d] * scale;
        const __nv_bfloat16 h = __float2bfloat16(v);
        const __nv_bfloat16 l = __float2bfloat16(v - __bfloat162float(h));
        *(unsigned short*)(sm + OFF_QH + r * AQP + d * 2) = __bfloat16_as_ushort(h);
        *(unsigned short*)(sm + OFF_QL + r * AQP + d * 2) = __bfloat16_as_ushort(l);
    }

    float of[16][4];
    #pragma unroll
    for (int n = 0; n < 16; ++n)
        #pragma unroll
        for (int r = 0; r < 4; ++r) of[n][r] = 0.f;
    float m0 = -3.0e38f, m1 = -3.0e38f, l0 = 0.f, l1 = 0.f;

    const int arow = lane & 15, achunk = lane >> 4;
    const int brow = lane & 7,  bchunk = (lane >> 3) & 1;
    const int rb = q0 + wid * 16;
    const int n_tiles = (q0 >> 6) + 2;

    for (int kt = 0; kt < n_tiles; ++kt) {
        __syncthreads();
        const int ktok = b * Sc + kt * 64;
        for (int idx = tid; idx < 64 * 128; idx += 256) {
            const int r = idx >> 7, d = idx & 127;
            const long long gk = (long long)(ktok + r) * QKVc + Dc + hh * HDc + d;
            const float kv = qkv[gk];
            __nv_bfloat16 h = __float2bfloat16(kv);
            __nv_bfloat16 l = __float2bfloat16(kv - __bfloat162float(h));
            *(unsigned short*)(sm + OFF_KH + r * AKP + d * 2) = __bfloat16_as_ushort(h);
            *(unsigned short*)(sm + OFF_KL + r * AKP + d * 2) = __bfloat16_as_ushort(l);
            const float vv = qkv[gk + Dc];
            h = __float2bfloat16(vv);
            l = __float2bfloat16(vv - __bfloat162float(h));
            *(unsigned short*)(sm + OFF_VH + d * AVP + r * 2) = __bfloat16_as_ushort(h);
            *(unsigned short*)(sm + OFF_VL + d * AVP + r * 2) = __bfloat16_as_ushort(l);
        }
        __syncthreads();

        float sfr[8][4];
        #pragma unroll
        for (int j = 0; j < 8; ++j)
            #pragma unroll
            for (int r = 0; r < 4; ++r) sfr[j][r] = 0.f;
        #pragma unroll
        for (int ks = 0; ks < 8; ++ks) {
            uint32_t qh[4], ql[4];
            const uint32_t qa = sb + OFF_QH + (wid * 16 + arow) * AQP + (ks * 2 + achunk) * 16;
            ldsm4(qh, qa);
            ldsm4(ql, qa + (OFF_QL - OFF_QH));
            #pragma unroll
            for (int j = 0; j < 8; ++j) {
                uint32_t kh2[2], kl2[2];
                const uint32_t ka = sb + OFF_KH + (8 * j + brow) * AKP + (ks * 2 + bchunk) * 16;
                ldsm2(kh2, ka);
                ldsm2(kl2, ka + (OFF_KL - OFF_KH));
                mma_bf16(sfr[j], qh, kh2);
                mma_bf16(sfr[j], qh, kl2);
                mma_bf16(sfr[j], ql, kh2);
            }
        }

        if (kt * 64 + 63 > rb) {
            #pragma unroll
            for (int j = 0; j < 8; ++j) {
                const int col = kt * 64 + 8 * j + 2 * qid;
                const int r0g = rb + grp, r1g = rb + grp + 8;
                if (col     > r0g) sfr[j][0] = -3.0e38f;
                if (col + 1 > r0g) sfr[j][1] = -3.0e38f;
                if (col     > r1g) sfr[j][2] = -3.0e38f;
                if (col + 1 > r1g) sfr[j][3] = -3.0e38f;
            }
        }

        float ml0 = -3.0e38f, ml1 = -3.0e38f;
        #pragma unroll
        for (int j = 0; j < 8; ++j) {
            ml0 = fmaxf(ml0, fmaxf(sfr[j][0], sfr[j][1]));
            ml1 = fmaxf(ml1, fmaxf(sfr[j][2], sfr[j][3]));
        }
        ml0 = fmaxf(ml0, __shfl_xor_sync(0xffffffffu, ml0, 1));
        ml0 = fmaxf(ml0, __shfl_xor_sync(0xffffffffu, ml0, 2));
        ml1 = fmaxf(ml1, __shfl_xor_sync(0xffffffffu, ml1, 1));
        ml1 = fmaxf(ml1, __shfl_xor_sync(0xffffffffu, ml1, 2));
        const float mn0 = fmaxf(m0, ml0), mn1 = fmaxf(m1, ml1);
        const float sc0 = expf(m0 - mn0), sc1 = expf(m1 - mn1);
        m0 = mn0; m1 = mn1;

        float rs0 = 0.f, rs1 = 0.f;
        uint32_t pah[4][4], pal[4][4];
        #pragma unroll
        for (int t = 0; t < 4; ++t) {
            const float p00 = expf(sfr[2*t][0] - mn0), p01 = expf(sfr[2*t][1] - mn0);
            const float p02 = expf(sfr[2*t][2] - mn1), p03 = expf(sfr[2*t][3] - mn1);
            const float p10 = expf(sfr[2*t+1][0] - mn0), p11 = expf(sfr[2*t+1][1] - mn0);
            const float p12 = expf(sfr[2*t+1][2] - mn1), p13 = expf(sfr[2*t+1][3] - mn1);
            rs0 += p00 + p01 + p10 + p11;
            rs1 += p02 + p03 + p12 + p13;
            split_pack2(p00, p01, pah[t][0], pal[t][0]);
            split_pack2(p02, p03, pah[t][1], pal[t][1]);
            split_pack2(p10, p11, pah[t][2], pal[t][2]);
            split_pack2(p12, p13, pah[t][3], pal[t][3]);
        }
        rs0 += __shfl_xor_sync(0xffffffffu, rs0, 1);
        rs0 += __shfl_xor_sync(0xffffffffu, rs0, 2);
        rs1 += __shfl_xor_sync(0xffffffffu, rs1, 1);
        rs1 += __shfl_xor_sync(0xffffffffu, rs1, 2);
        l0 = l0 * sc0 + rs0;
        l1 = l1 * sc1 + rs1;

        #pragma unroll
        for (int n = 0; n < 16; ++n) {
            of[n][0] *= sc0; of[n][1] *= sc0;
            of[n][2] *= sc1; of[n][3] *= sc1;
        }
        #pragma unroll
        for (int t = 0; t < 4; ++t) {
            #pragma unroll
            for (int n = 0; n < 16; ++n) {
                uint32_t vh2[2], vl2[2];
                const uint32_t va = sb + OFF_VH + (8 * n + brow) * AVP + (t * 2 + bchunk) * 16;
                ldsm2(vh2, va);
                ldsm2(vl2, va + (OFF_VL - OFF_VH));
                mma_bf16(of[n], pah[t], vh2);
                mma_bf16(of[n], pah[t], vl2);
                mma_bf16(of[n], pal[t], vh2);
            }
        }
    }

    const float li0 = 1.f / l0, li1 = 1.f / l1;
    const long long row0 = (long long)(tok0 + wid * 16 + grp);
    #pragma unroll
    for (int n = 0; n < 16; ++n) {
        const long long col = hh * HDc + 8 * n + 2 * qid;
        uint32_t h2, l2;
        split_pack2(of[n][0] * li0, of[n][1] * li0, h2, l2);
        *(uint32_t*)(oh + row0 * Dc + col) = h2;
        *(uint32_t*)(ol + row0 * Dc + col) = l2;
        split_pack2(of[n][2] * li1, of[n][3] * li1, h2, l2);
        *(uint32_t*)(oh + (row0 + 8) * Dc + col) = h2;
        *(uint32_t*)(ol + (row0 + 8) * Dc + col) = l2;
    }
}

// ---------------- launch ----------------------------------------------------
extern "C" void kernel_launch(void* const* d_in, const int* in_sizes, int n_in,
                              void* d_out, int out_size) {
    const int*   ids    = (const int*)  d_in[0];
    const int*   pos    = (const int*)  d_in[1];
    const float* embed  = (const float*)d_in[2];
    const float* Wqkv   = (const float*)d_in[3];
    const float* Wo     = (const float*)d_in[4];
    const float* Wgu    = (const float*)d_in[5];
    const float* Wd     = (const float*)d_in[6];
    const float* ln1    = (const float*)d_in[7];
    const float* ln2    = (const float*)d_in[8];
    const float* norm_w = (const float*)d_in[9];
    const float* lmh    = (const float*)d_in[10];
    float* out = (float*)d_out;

    float *h, *qkv;
    __nv_bfloat16 *xh, *xl, *oh, *ol, *ah, *al;
    __nv_bfloat16 *wqkvh, *wqkvl, *woh, *wol, *wguh, *wgul, *wdh, *wdl, *lmhh, *lmhl;
    cudaGetSymbolAddress((void**)&h,   g_h);
    cudaGetSymbolAddress((void**)&qkv, g_qkv);
    cudaGetSymbolAddress((void**)&xh,  g_xh);  cudaGetSymbolAddress((void**)&xl, g_xl);
    cudaGetSymbolAddress((void**)&oh,  g_oh);  cudaGetSymbolAddress((void**)&ol, g_ol);
    cudaGetSymbolAddress((void**)&ah,  g_ah);  cudaGetSymbolAddress((void**)&al, g_al);
    cudaGetSymbolAddress((void**)&wqkvh, g_wqkvh); cudaGetSymbolAddress((void**)&wqkvl, g_wqkvl);
    cudaGetSymbolAddress((void**)&woh,   g_woh);   cudaGetSymbolAddress((void**)&wol,   g_wol);
    cudaGetSymbolAddress((void**)&wguh,  g_wguh);  cudaGetSymbolAddress((void**)&wgul,  g_wgul);
    cudaGetSymbolAddress((void**)&wdh,   g_wdh);   cudaGetSymbolAddress((void**)&wdl,   g_wdl);
    cudaGetSymbolAddress((void**)&lmhh,  g_lmhh);  cudaGetSymbolAddress((void**)&lmhl,  g_lmhl);

    cudaFuncSetAttribute(attn_kernel,
                         cudaFuncAttributeMaxDynamicSharedMemorySize, ATTN_SMEM);
    cudaFuncSetAttribute(gemm_bf16x3,
                         cudaFuncAttributeMaxDynamicSharedMemorySize, GEMM_SMEM);

    // split all weights into bf16 hi/lo (Wgu gate/up-interleaved)
    {
        const long long n1 = (long long)Lc*QKVc*Dc, n2 = (long long)Lc*Dc*Dc,
                        n3 = (long long)Lc*GUc*Dc,  n4 = (long long)Lc*Dc*Ic,
                        n5 = (long long)Vc*Dc;
        split_kernel<<<(unsigned)((n1/4 + 255)/256), 256>>>(Wqkv, wqkvh, wqkvl, n1);
        split_kernel<<<(unsigned)((n2/4 + 255)/256), 256>>>(Wo,   woh,   wol,   n2);
        split_wgu_kernel<<<(unsigned)((n3/4 + 255)/256), 256>>>(Wgu, wguh, wgul);
        split_kernel<<<(unsigned)((n4/4 + 255)/256), 256>>>(Wd,   wdh,   wdl,   n4);
        split_kernel<<<(unsigned)((n5/4 + 255)/256), 256>>>(lmh,  lmhh,  lmhl,  n5);
    }

    embed_kernel<<<Tc, 128>>>(ids, embed, h);

    for (int l = 0; l < Lc; ++l) {
        rmsnorm_kernel<<<Tc, 256>>>(xh, xl, h, ln1 + (long long)l * Dc);
        gemm_bf16x3<<<dim3(Tc/128, QKVc/128), 256, GEMM_SMEM>>>(
            xh, xl, wqkvh + (long long)l*QKVc*Dc, wqkvl + (long long)l*QKVc*Dc,
            qkv, nullptr, nullptr, Tc, QKVc, Dc, 0);
        rope_kernel<<<(Tc * Hc * 64 + 255) / 256, 256>>>(qkv, pos);
        attn_kernel<<<dim3(Sc / 128, Hc, Bc), 256, ATTN_SMEM>>>(qkv, oh, ol);
        gemm_bf16x3<<<dim3(Tc/128, Dc/128), 256, GEMM_SMEM>>>(
            oh, ol, woh + (long long)l*Dc*Dc, wol + (long long)l*Dc*Dc,
            h, nullptr, nullptr, Tc, Dc, Dc, 1);
        rmsnorm_kernel<<<Tc, 256>>>(xh, xl, h, ln2 + (long long)l * Dc);
        gemm_bf16x3<<<dim3(Tc/128, GUc/128), 256, GEMM_SMEM>>>(
            xh, xl, wguh + (long long)l*GUc*Dc, wgul + (long long)l*GUc*Dc,
            nullptr, ah, al, Tc, GUc, Dc, 2);
        gemm_bf16x3<<<dim3(Tc/128, Dc/128), 256, GEMM_SMEM>>>(
            ah, al, wdh + (long long)l*Dc*Ic, wdl + (long long)l*Dc*Ic,
            h, nullptr, nullptr, Tc, Dc, Ic, 1);
    }

    rmsnorm_kernel<<<Tc, 256>>>(xh, xl, h, norm_w);
    gemm_bf16x3<<<dim3(Tc/128, Vc/128), 256, GEMM_SMEM>>>(
        xh, xl, lmhh, lmhl, out, nullptr, nullptr, Tc, Vc, Dc, 0);
}

// round 17
// speedup vs baseline: 1.0154x; 1.0001x over previous
#include <cuda_runtime.h>
#include <cuda_bf16.h>
#include <cstdint>

// Model dims
#define Lc   4
#define Dc   2048
#define Hc   16
#define HDc  128
#define Ic   5632
#define Vc   32000
#define Bc   2
#define Sc   1024
#define Tc   (Bc*Sc)        // 2048 tokens
#define QKVc (3*Hc*HDc)     // 6144
#define GUc  (2*Ic)         // 11264

// ---------------- scratch (static device globals; no allocations) ----------
__device__ float g_h  [Tc*Dc];     // residual (fp32)
__device__ float g_qkv[Tc*QKVc];   // qkv fp32 (attention input)

// split activations (bf16 hi/lo)
__device__ __nv_bfloat16 g_xh[Tc*Dc],  g_xl[Tc*Dc];
__device__ __nv_bfloat16 g_oh[Tc*Dc],  g_ol[Tc*Dc];
__device__ __nv_bfloat16 g_ah[Tc*Ic],  g_al[Tc*Ic];

// split weights (bf16 hi/lo); Wgu is stored gate/up row-interleaved
__device__ __nv_bfloat16 g_wqkvh[Lc*QKVc*Dc], g_wqkvl[Lc*QKVc*Dc];
__device__ __nv_bfloat16 g_woh  [Lc*Dc*Dc],   g_wol  [Lc*Dc*Dc];
__device__ __nv_bfloat16 g_wguh [Lc*GUc*Dc],  g_wgul [Lc*GUc*Dc];
__device__ __nv_bfloat16 g_wdh  [Lc*Dc*Ic],   g_wdl  [Lc*Dc*Ic];
__device__ __nv_bfloat16 g_lmhh [Vc*Dc],      g_lmhl [Vc*Dc];

// ---------------- small helpers --------------------------------------------
__device__ __forceinline__ uint32_t smem_u32(const void* p) {
    uint32_t a;
    asm("{ .reg .u64 t; cvta.to.shared.u64 t, %1; cvt.u32.u64 %0, t; }"
        : "=r"(a) : "l"(p));
    return a;
}
__device__ __forceinline__ void split_store4(__nv_bfloat16* hp, __nv_bfloat16* lp,
                                             long long off, float4 v) {
    __nv_bfloat16 h0 = __float2bfloat16(v.x), h1 = __float2bfloat16(v.y);
    __nv_bfloat16 h2 = __float2bfloat16(v.z), h3 = __float2bfloat16(v.w);
    __nv_bfloat16 l0 = __float2bfloat16(v.x - __bfloat162float(h0));
    __nv_bfloat16 l1 = __float2bfloat16(v.y - __bfloat162float(h1));
    __nv_bfloat16 l2 = __float2bfloat16(v.z - __bfloat162float(h2));
    __nv_bfloat16 l3 = __float2bfloat16(v.w - __bfloat162float(h3));
    *(ushort4*)(hp + off) = make_ushort4(__bfloat16_as_ushort(h0), __bfloat16_as_ushort(h1),
                                         __bfloat16_as_ushort(h2), __bfloat16_as_ushort(h3));
    *(ushort4*)(lp + off) = make_ushort4(__bfloat16_as_ushort(l0), __bfloat16_as_ushort(l1),
                                         __bfloat16_as_ushort(l2), __bfloat16_as_ushort(l3));
}
__device__ __forceinline__ void split_pack2(float a, float b,
                                            uint32_t& h, uint32_t& l) {
    __nv_bfloat16 ha = __float2bfloat16(a), hb = __float2bfloat16(b);
    __nv_bfloat16 la = __float2bfloat16(a - __bfloat162float(ha));
    __nv_bfloat16 lb = __float2bfloat16(b - __bfloat162float(hb));
    h = (uint32_t)__bfloat16_as_ushort(ha) | ((uint32_t)__bfloat16_as_ushort(hb) << 16);
    l = (uint32_t)__bfloat16_as_ushort(la) | ((uint32_t)__bfloat16_as_ushort(lb) << 16);
}

// ---------------- weight split ---------------------------------------------
__global__ void split_kernel(const float* __restrict__ s,
                             __nv_bfloat16* __restrict__ hp,
                             __nv_bfloat16* __restrict__ lp, long long n) {
    long long i = ((long long)blockIdx.x * blockDim.x + threadIdx.x) * 4;
    if (i >= n) return;
    split_store4(hp, lp, i, *(const float4*)(s + i));
}

// Wgu split with gate/up row interleave: dst row 2j = gate j, 2j+1 = up j.
__global__ void split_wgu_kernel(const float* __restrict__ s,
                                 __nv_bfloat16* __restrict__ hp,
                                 __nv_bfloat16* __restrict__ lp) {
    const long long total = (long long)Lc * GUc * Dc;
    long long i = ((long long)blockIdx.x * blockDim.x + threadIdx.x) * 4;
    if (i >= total) return;
    const long long layer = i / ((long long)GUc * Dc);
    const long long rem   = i - layer * (long long)GUc * Dc;
    const int nr = (int)(rem / Dc);          // interleaved dst row
    const int k  = (int)(rem - (long long)nr * Dc);
    const int sr = (nr & 1) ? (Ic + (nr >> 1)) : (nr >> 1);
    const long long src = layer * (long long)GUc * Dc + (long long)sr * Dc + k;
    split_store4(hp, lp, i, *(const float4*)(s + src));
}

// ---------------- embedding gather -----------------------------------------
__global__ void embed_kernel(const int* __restrict__ ids,
                             const float* __restrict__ emb,
                             float* __restrict__ h) {
    const int t = blockIdx.x;
    const int id = ids[t];
    const float4* src = (const float4*)(emb + (long long)id * Dc);
    float4* dst = (float4*)(h + (long long)t * Dc);
    for (int i = threadIdx.x; i < Dc / 4; i += blockDim.x) dst[i] = src[i];
}

// ---------------- rmsnorm -> split bf16 -------------------------------------
__global__ void __launch_bounds__(256) rmsnorm_kernel(
    __nv_bfloat16* __restrict__ oh, __nv_bfloat16* __restrict__ ol,
    const float* __restrict__ in, const float* __restrict__ w) {
    const int t = blockIdx.x;
    const int tid = threadIdx.x;
    const float4* row = (const float4*)(in + (long long)t * Dc);
    float4 v0 = row[tid];
    float4 v1 = row[tid + 256];
    float ss = v0.x*v0.x + v0.y*v0.y + v0.z*v0.z + v0.w*v0.w
             + v1.x*v1.x + v1.y*v1.y + v1.z*v1.z + v1.w*v1.w;
    #pragma unroll
    for (int m = 16; m >= 1; m >>= 1) ss += __shfl_xor_sync(0xffffffffu, ss, m);
    __shared__ float red[8];
    __shared__ float s_inv;
    if ((tid & 31) == 0) red[tid >> 5] = ss;
    __syncthreads();
    if (tid == 0) {
        float tot = 0.f;
        #pragma unroll
        for (int i = 0; i < 8; ++i) tot += red[i];
        s_inv = rsqrtf(tot * (1.0f / (float)Dc) + 1e-6f);
    }
    __syncthreads();
    const float inv = s_inv;
    const float4* wv = (const float4*)w;
    float4 w0 = wv[tid], w1 = wv[tid + 256];
    float4 o0 = make_float4(v0.x*inv*w0.x, v0.y*inv*w0.y, v0.z*inv*w0.z, v0.w*inv*w0.w);
    float4 o1 = make_float4(v1.x*inv*w1.x, v1.y*inv*w1.y, v1.z*inv*w1.z, v1.w*inv*w1.w);
    const long long base = (long long)t * Dc;
    split_store4(oh, ol, base + tid * 4, o0);
    split_store4(oh, ol, base + (tid + 256) * 4, o1);
}

// ---------------- rope ------------------------------------------------------
__global__ void rope_kernel(float* __restrict__ qkv, const int* __restrict__ pos) {
    const int idx = blockIdx.x * blockDim.x + threadIdx.x;
    if (idx >= Tc * Hc * (HDc / 2)) return;
    const int i  = idx & 63;
    const int hh = (idx >> 6) & (Hc - 1);
    const int t  = idx >> 10;
    const float freq = expf(-(float)i * (9.210340371976184f / 64.0f));
    const float ang  = (float)pos[t & (Sc - 1)] * freq;
    float s, c;
    sincosf(ang, &s, &c);
    const long long base = (long long)t * QKVc + hh * HDc + i;
    float q1 = qkv[base], q2 = qkv[base + 64];
    qkv[base]      = q1 * c - q2 * s;
    qkv[base + 64] = q2 * c + q1 * s;
    const long long kb = base + Dc;
    float k1 = qkv[kb], k2 = qkv[kb + 64];
    qkv[kb]      = k1 * c - k2 * s;
    qkv[kb + 64] = k2 * c + k1 * s;
}

// ---------------- bf16x3 NT GEMM (term-outer MMA order, single-sync loop) ---
// 8 warps (2m x 4n), warp tile 64x32, 128x128 CTA tile, BK=32, 2-stage cp.async.
// mode 0: store C; 1: C += ; 2: silu-fused (gate/up interleaved cols) -> Oh/Ol.
#define PITCH       80
#define TILE_BYTES  (128*PITCH)      // 10240
#define STAGE_BYTES (4*TILE_BYTES)   // 40960: Ah, Al, Bh, Bl
#define GEMM_SMEM   (2*STAGE_BYTES)  // 81920 -> 2 CTAs/SM

__device__ __forceinline__ void cp16(uint32_t dst, const void* src) {
    asm volatile("cp.async.cg.shared.global [%0], [%1], 16;" :: "r"(dst), "l"(src));
}
__device__ __forceinline__ void ldsm4(uint32_t* r, uint32_t addr) {
    asm volatile("ldmatrix.sync.aligned.m8n8.x4.shared.b16 {%0,%1,%2,%3}, [%4];"
                 : "=r"(r[0]), "=r"(r[1]), "=r"(r[2]), "=r"(r[3]) : "r"(addr));
}
__device__ __forceinline__ void ldsm2(uint32_t* r, uint32_t addr) {
    asm volatile("ldmatrix.sync.aligned.m8n8.x2.shared.b16 {%0,%1}, [%2];"
                 : "=r"(r[0]), "=r"(r[1]) : "r"(addr));
}
__device__ __forceinline__ void mma_bf16(float* c, const uint32_t* a, const uint32_t* b) {
    asm volatile(
        "mma.sync.aligned.m16n8k16.row.col.f32.bf16.bf16.f32 "
        "{%0,%1,%2,%3}, {%4,%5,%6,%7}, {%8,%9}, {%0,%1,%2,%3};"
        : "+f"(c[0]), "+f"(c[1]), "+f"(c[2]), "+f"(c[3])
        : "r"(a[0]), "r"(a[1]), "r"(a[2]), "r"(a[3]), "r"(b[0]), "r"(b[1]));
}
__device__ __forceinline__ float silu_mul(float g, float u) {
    return (g / (1.f + expf(-g))) * u;
}

__device__ __forceinline__ void load_stage(
    uint32_t sb, int s,
    const __nv_bfloat16* __restrict__ Ah, const __nv_bfloat16* __restrict__ Al,
    const __nv_bfloat16* __restrict__ Bh, const __nv_bfloat16* __restrict__ Bl,
    long long bm, long long bn, long long K, long long k0, int tid) {
    const __nv_bfloat16* gs[4] = {Ah, Al, Bh, Bl};
    #pragma unroll
    for (int t = 0; t < 4; ++t) {
        const long long row0 = (t < 2) ? bm : bn;
        const __nv_bfloat16* g = gs[t];
        #pragma unroll
        for (int u = 0; u < 2; ++u) {
            const int ch = tid + (u << 8);      // 0..511
            const int r = ch >> 2, c = ch & 3;  // row, 16B chunk
            const uint32_t dst = sb + s * STAGE_BYTES + t * TILE_BYTES
                               + r * PITCH + c * 16;
            cp16(dst, g + (row0 + r) * K + k0 + c * 8);
        }
    }
}

__global__ void __launch_bounds__(256) gemm_bf16x3(
    const __nv_bfloat16* __restrict__ Ah, const __nv_bfloat16* __restrict__ Al,
    const __nv_bfloat16* __restrict__ Bh, const __nv_bfloat16* __restrict__ Bl,
    float* __restrict__ C,
    __nv_bfloat16* __restrict__ Oh, __nv_bfloat16* __restrict__ Ol,
    int M, int N, int K, int mode) {
    extern __shared__ char smraw[];
    const uint32_t sb = smem_u32(smraw);
    const int tid  = threadIdx.x;
    const int wid  = tid >> 5;
    const int lane = tid & 31;
    const int grp  = lane >> 2;
    const int qid  = lane & 3;
    const int m_base = (wid >> 2) * 64;
    const int n_base = (wid & 3) * 32;
    const long long bm = (long long)blockIdx.x * 128;
    const long long bn = (long long)blockIdx.y * 128;

    float acc[4][4][4];
    #pragma unroll
    for (int i = 0; i < 4; ++i)
        #pragma unroll
        for (int j = 0; j < 4; ++j)
            #pragma unroll
            for (int r = 0; r < 4; ++r) acc[i][j][r] = 0.f;

    const int nIter = K >> 5;
    load_stage(sb, 0, Ah, Al, Bh, Bl, bm, bn, K, 0, tid);
    asm volatile("cp.async.commit_group;" ::: "memory");

    const int arow = lane & 15, achunk = lane >> 4;
    const int brow = lane & 7,  bchunk = (lane >> 3) & 1;

    for (int it = 0; it < nIter; ++it) {
        const int s = it & 1;
        asm volatile("cp.async.wait_group 0;" ::: "memory");
        __syncthreads();
        if (it + 1 < nIter) {
            load_stage(sb, s ^ 1, Ah, Al, Bh, Bl, bm, bn, K,
                       (long long)(it + 1) << 5, tid);
            asm volatile("cp.async.commit_group;" ::: "memory");
        }

        const uint32_t stb = sb + s * STAGE_BYTES;
        #pragma unroll
        for (int ks = 0; ks < 2; ++ks) {
            uint32_t ah[4][4], al[4][4], bh[4][2], bl[4][2];
            #pragma unroll
            for (int mt = 0; mt < 4; ++mt) {
                const uint32_t ad = stb + (m_base + mt * 16 + arow) * PITCH
                                  + (ks * 2 + achunk) * 16;
                ldsm4(ah[mt], ad);
                ldsm4(al[mt], ad + TILE_BYTES);
            }
            #pragma unroll
            for (int nt = 0; nt < 4; ++nt) {
                const uint32_t bd = stb + 2 * TILE_BYTES
                                  + (n_base + nt * 8 + brow) * PITCH
                                  + (ks * 2 + bchunk) * 16;
                ldsm2(bh[nt], bd);
                ldsm2(bl[nt], bd + TILE_BYTES);
            }
            // term-outer: 16 independent accumulators between successive
            // writes to the same acc -> no RAW chain. Per-acc summation
            // order (hh -> hl -> lh per k-step) unchanged => bit-identical.
            #pragma unroll
            for (int mt = 0; mt < 4; ++mt)
                #pragma unroll
                for (int nt = 0; nt < 4; ++nt)
                    mma_bf16(acc[mt][nt], ah[mt], bh[nt]);
            #pragma unroll
            for (int mt = 0; mt < 4; ++mt)
                #pragma unroll
                for (int nt = 0; nt < 4; ++nt)
                    mma_bf16(acc[mt][nt], ah[mt], bl[nt]);
            #pragma unroll
            for (int mt = 0; mt < 4; ++mt)
                #pragma unroll
                for (int nt = 0; nt < 4; ++nt)
                    mma_bf16(acc[mt][nt], al[mt], bh[nt]);
        }
    }

    if (mode == 2) {
        // silu-fused: even col = gate, odd col = up; output width N/2
        const int NO = N >> 1;
        #pragma unroll
        for (int mt = 0; mt < 4; ++mt) {
            #pragma unroll
            for (int nt = 0; nt < 4; ++nt) {
                const long long row = bm + m_base + mt * 16 + grp;
                const long long col = (bn + n_base + nt * 8 + 2 * qid) >> 1;
                float* c = acc[mt][nt];
                const float a0 = silu_mul(c[0], c[1]);
                const float a1 = silu_mul(c[2], c[3]);
                __nv_bfloat16 h0 = __float2bfloat16(a0);
                __nv_bfloat16 l0 = __float2bfloat16(a0 - __bfloat162float(h0));
                __nv_bfloat16 h1 = __float2bfloat16(a1);
                __nv_bfloat16 l1 = __float2bfloat16(a1 - __bfloat162float(h1));
                Oh[row * NO + col] = h0;  Ol[row * NO + col] = l0;
                Oh[(row + 8) * NO + col] = h1;  Ol[(row + 8) * NO + col] = l1;
            }
        }
        return;
    }

    #pragma unroll
    for (int mt = 0; mt < 4; ++mt) {
        #pragma unroll
        for (int nt = 0; nt < 4; ++nt) {
            const long long row = bm + m_base + mt * 16 + grp;
            const long long col = bn + n_base + nt * 8 + 2 * qid;
            float* c = acc[mt][nt];
            if (mode == 1) {
                float2 r0 = *(const float2*)&C[row * N + col];
                float2 r1 = *(const float2*)&C[(row + 8) * N + col];
                c[0] += r0.x; c[1] += r0.y; c[2] += r1.x; c[3] += r1.y;
            }
            *(float2*)&C[row * N + col]       = make_float2(c[0], c[1]);
            *(float2*)&C[(row + 8) * N + col] = make_float2(c[2], c[3]);
        }
    }
}

// ---------------- tensor-core flash attention (bf16x3) ----------------------
#define AQP 272   // Q row pitch: 128 bf16 = 256B + 16 pad
#define AKP 272   // K row pitch
#define AVP 144   // V^T row pitch: 64 bf16 = 128B + 16 pad
#define OFF_QH 0
#define OFF_QL (128*AQP)
#define OFF_KH (2*128*AQP)
#define OFF_KL (OFF_KH + 64*AKP)
#define OFF_VH (OFF_KL + 64*AKP)
#define OFF_VL (OFF_VH + 128*AVP)
#define ATTN_SMEM (OFF_VL + 128*AVP)   // 141312 bytes

__global__ void __launch_bounds__(256) attn_kernel(
    const float* __restrict__ qkv,
    __nv_bfloat16* __restrict__ oh, __nv_bfloat16* __restrict__ ol) {
    extern __shared__ char sm[];
    const uint32_t sb = smem_u32(sm);
    const int tid = threadIdx.x, wid = tid >> 5, lane = tid & 31;
    const int grp = lane >> 2, qid = lane & 3;
    const int qt = (int)gridDim.x - 1 - (int)blockIdx.x;  // heavy first
    const int hh = blockIdx.y, b = blockIdx.z;
    const int q0 = qt * 128;
    const int tok0 = b * Sc + q0;
    const float scale = 0.08838834764831845f;

    for (int idx = tid; idx < 128 * 128; idx += 256) {
        const int r = idx >> 7, d = idx & 127;
        const float v = qkv[(long long)(tok0 + r) * QKVc + hh * HDc + d] * scale;
        const __nv_bfloat16 h = __float2bfloat16(v);
        const __nv_bfloat16 l = __float2bfloat16(v - __bfloat162float(h));
        *(unsigned short*)(sm + OFF_QH + r * AQP + d * 2) = __bfloat16_as_ushort(h);
        *(unsigned short*)(sm + OFF_QL + r * AQP + d * 2) = __bfloat16_as_ushort(l);
    }

    float of[16][4];
    #pragma unroll
    for (int n = 0; n < 16; ++n)
        #pragma unroll
        for (int r = 0; r < 4; ++r) of[n][r] = 0.f;
    float m0 = -3.0e38f, m1 = -3.0e38f, l0 = 0.f, l1 = 0.f;

    const int arow = lane & 15, achunk = lane >> 4;
    const int brow = lane & 7,  bchunk = (lane >> 3) & 1;
    const int rb = q0 + wid * 16;
    const int n_tiles = (q0 >> 6) + 2;

    for (int kt = 0; kt < n_tiles; ++kt) {
        __syncthreads();
        const int ktok = b * Sc + kt * 64;
        for (int idx = tid; idx < 64 * 128; idx += 256) {
            const int r = idx >> 7, d = idx & 127;
            const long long gk = (long long)(ktok + r) * QKVc + Dc + hh * HDc + d;
            const float kv = qkv[gk];
            __nv_bfloat16 h = __float2bfloat16(kv);
            __nv_bfloat16 l = __float2bfloat16(kv - __bfloat162float(h));
            *(unsigned short*)(sm + OFF_KH + r * AKP + d * 2) = __bfloat16_as_ushort(h);
            *(unsigned short*)(sm + OFF_KL + r * AKP + d * 2) = __bfloat16_as_ushort(l);
            const float vv = qkv[gk + Dc];
            h = __float2bfloat16(vv);
            l = __float2bfloat16(vv - __bfloat162float(h));
            *(unsigned short*)(sm + OFF_VH + d * AVP + r * 2) = __bfloat16_as_ushort(h);
            *(unsigned short*)(sm + OFF_VL + d * AVP + r * 2) = __bfloat16_as_ushort(l);
        }
        __syncthreads();

        float sfr[8][4];
        #pragma unroll
        for (int j = 0; j < 8; ++j)
            #pragma unroll
            for (int r = 0; r < 4; ++r) sfr[j][r] = 0.f;
        #pragma unroll
        for (int ks = 0; ks < 8; ++ks) {
            uint32_t qh[4], ql[4];
            const uint32_t qa = sb + OFF_QH + (wid * 16 + arow) * AQP + (ks * 2 + achunk) * 16;
            ldsm4(qh, qa);
            ldsm4(ql, qa + (OFF_QL - OFF_QH));
            #pragma unroll
            for (int j = 0; j < 8; ++j) {
                uint32_t kh2[2], kl2[2];
                const uint32_t ka = sb + OFF_KH + (8 * j + brow) * AKP + (ks * 2 + bchunk) * 16;
                ldsm2(kh2, ka);
                ldsm2(kl2, ka + (OFF_KL - OFF_KH));
                mma_bf16(sfr[j], qh, kh2);
                mma_bf16(sfr[j], qh, kl2);
                mma_bf16(sfr[j], ql, kh2);
            }
        }

        if (kt * 64 + 63 > rb) {
            #pragma unroll
            for (int j = 0; j < 8; ++j) {
                const int col = kt * 64 + 8 * j + 2 * qid;
                const int r0g = rb + grp, r1g = rb + grp + 8;
                if (col     > r0g) sfr[j][0] = -3.0e38f;
                if (col + 1 > r0g) sfr[j][1] = -3.0e38f;
                if (col     > r1g) sfr[j][2] = -3.0e38f;
                if (col + 1 > r1g) sfr[j][3] = -3.0e38f;
            }
        }

        float ml0 = -3.0e38f, ml1 = -3.0e38f;
        #pragma unroll
        for (int j = 0; j < 8; ++j) {
            ml0 = fmaxf(ml0, fmaxf(sfr[j][0], sfr[j][1]));
            ml1 = fmaxf(ml1, fmaxf(sfr[j][2], sfr[j][3]));
        }
        ml0 = fmaxf(ml0, __shfl_xor_sync(0xffffffffu, ml0, 1));
        ml0 = fmaxf(ml0, __shfl_xor_sync(0xffffffffu, ml0, 2));
        ml1 = fmaxf(ml1, __shfl_xor_sync(0xffffffffu, ml1, 1));
        ml1 = fmaxf(ml1, __shfl_xor_sync(0xffffffffu, ml1, 2));
        const float mn0 = fmaxf(m0, ml0), mn1 = fmaxf(m1, ml1);
        const float sc0 = expf(m0 - mn0), sc1 = expf(m1 - mn1);
        m0 = mn0; m1 = mn1;

        float rs0 = 0.f, rs1 = 0.f;
        uint32_t pah[4][4], pal[4][4];
        #pragma unroll
        for (int t = 0; t < 4; ++t) {
            const float p00 = expf(sfr[2*t][0] - mn0), p01 = expf(sfr[2*t][1] - mn0);
            const float p02 = expf(sfr[2*t][2] - mn1), p03 = expf(sfr[2*t][3] - mn1);
            const float p10 = expf(sfr[2*t+1][0] - mn0), p11 = expf(sfr[2*t+1][1] - mn0);
            const float p12 = expf(sfr[2*t+1][2] - mn1), p13 = expf(sfr[2*t+1][3] - mn1);
            rs0 += p00 + p01 + p10 + p11;
            rs1 += p02 + p03 + p12 + p13;
            split_pack2(p00, p01, pah[t][0], pal[t][0]);
            split_pack2(p02, p03, pah[t][1], pal[t][1]);
            split_pack2(p10, p11, pah[t][2], pal[t][2]);
            split_pack2(p12, p13, pah[t][3], pal[t][3]);
        }
        rs0 += __shfl_xor_sync(0xffffffffu, rs0, 1);
        rs0 += __shfl_xor_sync(0xffffffffu, rs0, 2);
        rs1 += __shfl_xor_sync(0xffffffffu, rs1, 1);
        rs1 += __shfl_xor_sync(0xffffffffu, rs1, 2);
        l0 = l0 * sc0 + rs0;
        l1 = l1 * sc1 + rs1;

        #pragma unroll
        for (int n = 0; n < 16; ++n) {
            of[n][0] *= sc0; of[n][1] *= sc0;
            of[n][2] *= sc1; of[n][3] *= sc1;
        }
        #pragma unroll
        for (int t = 0; t < 4; ++t) {
            #pragma unroll
            for (int n = 0; n < 16; ++n) {
                uint32_t vh2[2], vl2[2];
                const uint32_t va = sb + OFF_VH + (8 * n + brow) * AVP + (t * 2 + bchunk) * 16;
                ldsm2(vh2, va);
                ldsm2(vl2, va + (OFF_VL - OFF_VH));
                mma_bf16(of[n], pah[t], vh2);
                mma_bf16(of[n], pah[t], vl2);
                mma_bf16(of[n], pal[t], vh2);
            }
        }
    }

    const float li0 = 1.f / l0, li1 = 1.f / l1;
    const long long row0 = (long long)(tok0 + wid * 16 + grp);
    #pragma unroll
    for (int n = 0; n < 16; ++n) {
        const long long col = hh * HDc + 8 * n + 2 * qid;
        uint32_t h2, l2;
        split_pack2(of[n][0] * li0, of[n][1] * li0, h2, l2);
        *(uint32_t*)(oh + row0 * Dc + col) = h2;
        *(uint32_t*)(ol + row0 * Dc + col) = l2;
        split_pack2(of[n][2] * li1, of[n][3] * li1, h2, l2);
        *(uint32_t*)(oh + (row0 + 8) * Dc + col) = h2;
        *(uint32_t*)(ol + (row0 + 8) * Dc + col) = l2;
    }
}

// ---------------- launch ----------------------------------------------------
extern "C" void kernel_launch(void* const* d_in, const int* in_sizes, int n_in,
                              void* d_out, int out_size) {
    const int*   ids    = (const int*)  d_in[0];
    const int*   pos    = (const int*)  d_in[1];
    const float* embed  = (const float*)d_in[2];
    const float* Wqkv   = (const float*)d_in[3];
    const float* Wo     = (const float*)d_in[4];
    const float* Wgu    = (const float*)d_in[5];
    const float* Wd     = (const float*)d_in[6];
    const float* ln1    = (const float*)d_in[7];
    const float* ln2    = (const float*)d_in[8];
    const float* norm_w = (const float*)d_in[9];
    const float* lmh    = (const float*)d_in[10];
    float* out = (float*)d_out;

    float *h, *qkv;
    __nv_bfloat16 *xh, *xl, *oh, *ol, *ah, *al;
    __nv_bfloat16 *wqkvh, *wqkvl, *woh, *wol, *wguh, *wgul, *wdh, *wdl, *lmhh, *lmhl;
    cudaGetSymbolAddress((void**)&h,   g_h);
    cudaGetSymbolAddress((void**)&qkv, g_qkv);
    cudaGetSymbolAddress((void**)&xh,  g_xh);  cudaGetSymbolAddress((void**)&xl, g_xl);
    cudaGetSymbolAddress((void**)&oh,  g_oh);  cudaGetSymbolAddress((void**)&ol, g_ol);
    cudaGetSymbolAddress((void**)&ah,  g_ah);  cudaGetSymbolAddress((void**)&al, g_al);
    cudaGetSymbolAddress((void**)&wqkvh, g_wqkvh); cudaGetSymbolAddress((void**)&wqkvl, g_wqkvl);
    cudaGetSymbolAddress((void**)&woh,   g_woh);   cudaGetSymbolAddress((void**)&wol,   g_wol);
    cudaGetSymbolAddress((void**)&wguh,  g_wguh);  cudaGetSymbolAddress((void**)&wgul,  g_wgul);
    cudaGetSymbolAddress((void**)&wdh,   g_wdh);   cudaGetSymbolAddress((void**)&wdl,   g_wdl);
    cudaGetSymbolAddress((void**)&lmhh,  g_lmhh);  cudaGetSymbolAddress((void**)&lmhl,  g_lmhl);

    cudaFuncSetAttribute(attn_kernel,
                         cudaFuncAttributeMaxDynamicSharedMemorySize, ATTN_SMEM);
    cudaFuncSetAttribute(gemm_bf16x3,
                         cudaFuncAttributeMaxDynamicSharedMemorySize, GEMM_SMEM);

    // split all weights into bf16 hi/lo (Wgu gate/up-interleaved)
    {
        const long long n1 = (long long)Lc*QKVc*Dc, n2 = (long long)Lc*Dc*Dc,
                        n3 = (long long)Lc*GUc*Dc,  n4 = (long long)Lc*Dc*Ic,
                        n5 = (long long)Vc*Dc;
        split_kernel<<<(unsigned)((n1/4 + 255)/256), 256>>>(Wqkv, wqkvh, wqkvl, n1);
        split_kernel<<<(unsigned)((n2/4 + 255)/256), 256>>>(Wo,   woh,   wol,   n2);
        split_wgu_kernel<<<(unsigned)((n3/4 + 255)/256), 256>>>(Wgu, wguh, wgul);
        split_kernel<<<(unsigned)((n4/4 + 255)/256), 256>>>(Wd,   wdh,   wdl,   n4);
        split_kernel<<<(unsigned)((n5/4 + 255)/256), 256>>>(lmh,  lmhh,  lmhl,  n5);
    }

    embed_kernel<<<Tc, 128>>>(ids, embed, h);

    for (int l = 0; l < Lc; ++l) {
        rmsnorm_kernel<<<Tc, 256>>>(xh, xl, h, ln1 + (long long)l * Dc);
        gemm_bf16x3<<<dim3(Tc/128, QKVc/128), 256, GEMM_SMEM>>>(
            xh, xl, wqkvh + (long long)l*QKVc*Dc, wqkvl + (long long)l*QKVc*Dc,
            qkv, nullptr, nullptr, Tc, QKVc, Dc, 0);
        rope_kernel<<<(Tc * Hc * 64 + 255) / 256, 256>>>(qkv, pos);
        attn_kernel<<<dim3(Sc / 128, Hc, Bc), 256, ATTN_SMEM>>>(qkv, oh, ol);
        gemm_bf16x3<<<dim3(Tc/128, Dc/128), 256, GEMM_SMEM>>>(
            oh, ol, woh + (long long)l*Dc*Dc, wol + (long long)l*Dc*Dc,
            h, nullptr, nullptr, Tc, Dc, Dc, 1);
        rmsnorm_kernel<<<Tc, 256>>>(xh, xl, h, ln2 + (long long)l * Dc);
        gemm_bf16x3<<<dim3(Tc/128, GUc/128), 256, GEMM_SMEM>>>(
            xh, xl, wguh + (long long)l*GUc*Dc, wgul + (long long)l*GUc*Dc,
            nullptr, ah, al, Tc, GUc, Dc, 2);
        gemm_bf16x3<<<dim3(Tc/128, Dc/128), 256, GEMM_SMEM>>>(
            ah, al, wdh + (long long)l*Dc*Ic, wdl + (long long)l*Dc*Ic,
            h, nullptr, nullptr, Tc, Dc, Ic, 1);
    }

    rmsnorm_kernel<<<Tc, 256>>>(xh, xl, h, norm_w);
    gemm_bf16x3<<<dim3(Tc/128, Vc/128), 256, GEMM_SMEM>>>(
        xh, xl, lmhh, lmhl, out, nullptr, nullptr, Tc, Vc, Dc, 0);
}